// round 8
// baseline (speedup 1.0000x reference)
#include <cuda_runtime.h>
#include <math.h>
#include <stdint.h>

// ---------------------------------------------------------------------------
// Problem constants
// ---------------------------------------------------------------------------
#define NLAYERS 4
#define NB      4
#define SQ      512
#define DM      512
#define NH      8
#define DH      64
#define MEMN    512
#define CMEMN   128
#define RRATIO  4
#define LLAT    256
#define FFD     2048
#define KVN     (CMEMN + MEMN + SQ)   // 1152
#define MROWS   (NB * SQ)             // 2048

// ---------------------------------------------------------------------------
// Scratch (device globals)
// ---------------------------------------------------------------------------
__device__ float g_x  [MROWS * DM];
__device__ float g_kv [NB * KVN * DM];
__device__ float g_q  [MROWS * DM];
__device__ float g_k  [NB * KVN * DM];
__device__ float g_v  [NB * KVN * DM];
__device__ float g_dots[(size_t)NB * NH * SQ * KVN];
__device__ float g_pos [(size_t)NB * NH * SQ * KVN];
__device__ float g_ao [MROWS * DM];
__device__ float g_t1 [MROWS * DM];
__device__ float g_t2 [MROWS * DM];
__device__ float g_cm [NB * CMEMN * DM];
__device__ float g_kcm[NB * CMEMN * DM];
__device__ float g_vcm[NB * CMEMN * DM];
__device__ float g_y  [MROWS * DM];
__device__ float g_ff [MROWS * FFD];
__device__ float g_wc [NLAYERS * RRATIO * DM * DM];
__device__ float g_sk [4 * 1024 * 1024];          // split-K partials
__device__ float g_part[NLAYERS * 128];

// ---------------------------------------------------------------------------
// Packed fp32x2 helpers (Blackwell FFMA2)
// ---------------------------------------------------------------------------
__device__ __forceinline__ unsigned long long pk2(float lo, float hi) {
    unsigned long long r;
    asm("mov.b64 %0, {%1,%2};" : "=l"(r) : "f"(lo), "f"(hi));
    return r;
}
__device__ __forceinline__ void upk2(unsigned long long v, float& lo, float& hi) {
    asm("mov.b64 {%0,%1}, %2;" : "=f"(lo), "=f"(hi) : "l"(v));
}
__device__ __forceinline__ void fma2(unsigned long long& d, unsigned long long a,
                                     unsigned long long b) {
    asm("fma.rn.f32x2 %0, %1, %2, %0;" : "+l"(d) : "l"(a), "l"(b));
}

// ===========================================================================
// BIG GEMM: BM=128, BN=128, BK=16, 256 threads, 8x8 outputs/thread.
// A smem: [k][m] (u64 pairs along m, read directly as b64, no packing).
// B smem: duplicated pairs (b,b) per value, strided column map c=col0+tx+16t
//         -> conflict-free LDS.64, coalesced STG.32 epilogue.
// Dynamic smem: As 2*16*132 floats + Bdup 2*16*256 floats = 49664 B.
// EPI: 0 = none, 3 = gelu(x + bias)
// ===========================================================================
#define SMEM_BIG ((2*16*132 + 2*16*256) * 4)

template<int EPI>
__device__ __forceinline__ void gemm128_body(
    const float* __restrict__ A, const float* __restrict__ Bw, float* __restrict__ C,
    int N, int K, int kBeg, int kEnd, const float* __restrict__ bias)
{
    extern __shared__ float smem[];
    float* AsF = smem;                     // [2][16][132]
    unsigned long long* BsD = (unsigned long long*)(smem + 2 * 16 * 132); // [2][16][128] u64

    const int tid  = threadIdx.x;
    const int tx   = tid & 15, ty = tid >> 4;
    const int row0 = blockIdx.y * 128, col0 = blockIdx.x * 128;
    const int ar   = tid >> 2,  ak = (tid & 3) << 2;     // A fill: row, k-offset
    const int brB  = tid >> 4,  nb0 = tid & 15;          // B fill: k-row, col base
    const float* Ag = A + (size_t)row0 * K + kBeg;
    const float* Bg = Bw + (size_t)kBeg * N + col0;

    unsigned long long acc[4][8];
#pragma unroll
    for (int m = 0; m < 4; m++)
#pragma unroll
        for (int t = 0; t < 8; t++) acc[m][t] = 0ull;

    const int nk = (kEnd - kBeg) >> 4;

    // ---- preload tile 0 ----
    float4 a0 = *(const float4*)(Ag + (size_t)ar        * K + ak);
    float4 a1 = *(const float4*)(Ag + (size_t)(ar + 64) * K + ak);
    float bpre[8];
#pragma unroll
    for (int t = 0; t < 8; t++) bpre[t] = Bg[(size_t)brB * N + nb0 + 16 * t];
    {
        float* As0 = AsF;                              // buf 0
        As0[(ak+0)*132 + ar] = a0.x; As0[(ak+1)*132 + ar] = a0.y;
        As0[(ak+2)*132 + ar] = a0.z; As0[(ak+3)*132 + ar] = a0.w;
        As0[(ak+0)*132 + ar+64] = a1.x; As0[(ak+1)*132 + ar+64] = a1.y;
        As0[(ak+2)*132 + ar+64] = a1.z; As0[(ak+3)*132 + ar+64] = a1.w;
        unsigned long long* Bs0 = BsD;
#pragma unroll
        for (int t = 0; t < 8; t++)
            Bs0[brB * 128 + nb0 + 16 * t] = pk2(bpre[t], bpre[t]);
    }
    __syncthreads();

    int buf = 0;
    for (int t2 = 0; t2 < nk; t2++) {
        const bool more = (t2 + 1 < nk);
        if (more) {
            const float* Ag2 = Ag + (t2 + 1) * 16;
            a0 = *(const float4*)(Ag2 + (size_t)ar        * K + ak);
            a1 = *(const float4*)(Ag2 + (size_t)(ar + 64) * K + ak);
            const float* Bg2 = Bg + (size_t)((t2 + 1) * 16) * N;
#pragma unroll
            for (int t = 0; t < 8; t++) bpre[t] = Bg2[(size_t)brB * N + nb0 + 16 * t];
        }
        // ---- compute on buf ----
        const unsigned long long* Ap =
            (const unsigned long long*)(AsF + buf * (16 * 132)) + ty * 4;  // row stride 66 u64
        const unsigned long long* Bp = BsD + buf * (16 * 128) + tx;
#pragma unroll
        for (int k = 0; k < 16; k++) {
            unsigned long long am0 = Ap[k*66 + 0];
            unsigned long long am1 = Ap[k*66 + 1];
            unsigned long long am2 = Ap[k*66 + 2];
            unsigned long long am3 = Ap[k*66 + 3];
#pragma unroll
            for (int t = 0; t < 8; t++) {
                unsigned long long bd = Bp[k*128 + 16*t];
                fma2(acc[0][t], am0, bd);
                fma2(acc[1][t], am1, bd);
                fma2(acc[2][t], am2, bd);
                fma2(acc[3][t], am3, bd);
            }
        }
        if (more) {
            float* Asn = AsF + (buf ^ 1) * (16 * 132);
            Asn[(ak+0)*132 + ar] = a0.x; Asn[(ak+1)*132 + ar] = a0.y;
            Asn[(ak+2)*132 + ar] = a0.z; Asn[(ak+3)*132 + ar] = a0.w;
            Asn[(ak+0)*132 + ar+64] = a1.x; Asn[(ak+1)*132 + ar+64] = a1.y;
            Asn[(ak+2)*132 + ar+64] = a1.z; Asn[(ak+3)*132 + ar+64] = a1.w;
            unsigned long long* Bsn = BsD + (buf ^ 1) * (16 * 128);
#pragma unroll
            for (int t = 0; t < 8; t++)
                Bsn[brB * 128 + nb0 + 16 * t] = pk2(bpre[t], bpre[t]);
        }
        __syncthreads();
        buf ^= 1;
    }

    // ---- epilogue: rows row0+ty*8+2m+{0,1}, cols col0+tx+16t ----
#pragma unroll
    for (int m = 0; m < 4; m++) {
        const int r = row0 + ty * 8 + 2 * m;
#pragma unroll
        for (int t = 0; t < 8; t++) {
            const int c = col0 + tx + 16 * t;
            float lo, hi;
            upk2(acc[m][t], lo, hi);
            if (EPI == 3) {
                const float bb = bias[c];
                lo += bb; hi += bb;
                lo = 0.5f * lo * (1.0f + erff(lo * 0.70710678118654752440f));
                hi = 0.5f * hi * (1.0f + erff(hi * 0.70710678118654752440f));
            }
            C[(size_t)r       * N + c] = lo;
            C[(size_t)(r + 1) * N + c] = hi;
        }
    }
}

// z-batched big SGEMM (up to 3 problems sharing N, K)
template<int EPI>
__global__ __launch_bounds__(256, 2) void sgemm_big_t(
    const float* A0, const float* B0, float* C0, int M0,
    const float* A1, const float* B1, float* C1, int M1,
    const float* A2, const float* B2, float* C2, int M2,
    int N, int K, const float* bias)
{
    const int z = blockIdx.z;
    const float* A  = (z == 0) ? A0 : (z == 1) ? A1 : A2;
    const float* Bw = (z == 0) ? B0 : (z == 1) ? B1 : B2;
    float*       C  = (z == 0) ? C0 : (z == 1) ? C1 : C2;
    const int    M  = (z == 0) ? M0 : (z == 1) ? M1 : M2;
    if (blockIdx.y * 128 >= M) return;
    gemm128_body<EPI>(A, Bw, C, N, K, 0, K, bias);
}

// split-K big SGEMM
__global__ __launch_bounds__(256, 2) void sgemm_big_splitk(
    const float* A, const float* Bw, float* Cpart, int M, int N, int K, int KC)
{
    const int z = blockIdx.z;
    gemm128_body<0>(A, Bw, Cpart + (size_t)z * M * N, N, K, z * KC, z * KC + KC, nullptr);
}

// ===========================================================================
// SMALL GEMM (previous 8x4 kernel) — for the low-block-count GEMMs
// ===========================================================================
__device__ __forceinline__ void gemm_body(
    const float* __restrict__ A, const float* __restrict__ Bw, float* __restrict__ C,
    int N, int K, int kBeg, int kEnd,
    int epi, const float* __restrict__ bias, const float* __restrict__ resid)
{
    __shared__ __align__(16) float As[2][16][132];
    __shared__ __align__(16) float Bs[2][16][64];
    const int tid  = threadIdx.x;
    const int tx   = tid & 15, ty = tid >> 4;
    const int row0 = blockIdx.y * 128, col0 = blockIdx.x * 64;
    const int ar   = tid >> 2,  ak = (tid & 3) << 2;
    const int br   = tid >> 4,  bc = (tid & 15) << 2;
    const float* Ag = A + (size_t)row0 * K + kBeg;
    const float* Bg = Bw + (size_t)kBeg * N + col0;

    unsigned long long acc[4][4];
#pragma unroll
    for (int m = 0; m < 4; m++)
#pragma unroll
        for (int n = 0; n < 4; n++) acc[m][n] = 0ull;

    const int nk = (kEnd - kBeg) >> 4;
    float4 a0 = *(const float4*)(Ag + (size_t)ar        * K + ak);
    float4 a1 = *(const float4*)(Ag + (size_t)(ar + 64) * K + ak);
    float4 b0 = *(const float4*)(Bg + (size_t)br * N + bc);
    As[0][ak+0][ar]    = a0.x; As[0][ak+1][ar]    = a0.y; As[0][ak+2][ar]    = a0.z; As[0][ak+3][ar]    = a0.w;
    As[0][ak+0][ar+64] = a1.x; As[0][ak+1][ar+64] = a1.y; As[0][ak+2][ar+64] = a1.z; As[0][ak+3][ar+64] = a1.w;
    *(float4*)&Bs[0][br][bc] = b0;
    __syncthreads();

    int buf = 0;
    for (int t = 0; t < nk; t++) {
        const bool more = (t + 1 < nk);
        if (more) {
            const float* Ag2 = Ag + (t + 1) * 16;
            a0 = *(const float4*)(Ag2 + (size_t)ar        * K + ak);
            a1 = *(const float4*)(Ag2 + (size_t)(ar + 64) * K + ak);
            b0 = *(const float4*)(Bg + (size_t)((t + 1) * 16 + br) * N + bc);
        }
#pragma unroll
        for (int k = 0; k < 16; k++) {
            float4 av0 = *(const float4*)&As[buf][k][ty*8];
            float4 av1 = *(const float4*)&As[buf][k][ty*8 + 4];
            float4 bv  = *(const float4*)&Bs[buf][k][tx*4];
            unsigned long long am[4] = { pk2(av0.x, av0.y), pk2(av0.z, av0.w),
                                         pk2(av1.x, av1.y), pk2(av1.z, av1.w) };
            unsigned long long bd[4] = { pk2(bv.x, bv.x), pk2(bv.y, bv.y),
                                         pk2(bv.z, bv.z), pk2(bv.w, bv.w) };
#pragma unroll
            for (int m = 0; m < 4; m++)
#pragma unroll
                for (int n = 0; n < 4; n++) fma2(acc[m][n], am[m], bd[n]);
        }
        if (more) {
            const int nb = buf ^ 1;
            As[nb][ak+0][ar]    = a0.x; As[nb][ak+1][ar]    = a0.y; As[nb][ak+2][ar]    = a0.z; As[nb][ak+3][ar]    = a0.w;
            As[nb][ak+0][ar+64] = a1.x; As[nb][ak+1][ar+64] = a1.y; As[nb][ak+2][ar+64] = a1.z; As[nb][ak+3][ar+64] = a1.w;
            *(float4*)&Bs[nb][br][bc] = b0;
        }
        __syncthreads();
        buf ^= 1;
    }

    const int c0 = col0 + tx * 4;
#pragma unroll
    for (int m2 = 0; m2 < 4; m2++) {
        const int r = row0 + ty * 8 + m2 * 2;
        float lo[4], hi[4];
#pragma unroll
        for (int n = 0; n < 4; n++) upk2(acc[m2][n], lo[n], hi[n]);
        if (epi == 2 || epi == 4) {
            float4 bb = *(const float4*)(bias + c0);
            lo[0]+=bb.x; lo[1]+=bb.y; lo[2]+=bb.z; lo[3]+=bb.w;
            hi[0]+=bb.x; hi[1]+=bb.y; hi[2]+=bb.z; hi[3]+=bb.w;
        }
        if (epi == 1 || epi == 4) {
            float4 r0 = *(const float4*)(resid + (size_t)r * N + c0);
            float4 r1 = *(const float4*)(resid + (size_t)(r + 1) * N + c0);
            lo[0]+=r0.x; lo[1]+=r0.y; lo[2]+=r0.z; lo[3]+=r0.w;
            hi[0]+=r1.x; hi[1]+=r1.y; hi[2]+=r1.z; hi[3]+=r1.w;
        }
        *(float4*)(C + (size_t)r       * N + c0) = make_float4(lo[0], lo[1], lo[2], lo[3]);
        *(float4*)(C + (size_t)(r + 1) * N + c0) = make_float4(hi[0], hi[1], hi[2], hi[3]);
    }
}

__global__ __launch_bounds__(256, 2) void sgemm_k(
    const float* A0, const float* B0, float* C0, int M0,
    const float* A1, const float* B1, float* C1, int M1,
    int N, int K, int epi, const float* bias, const float* resid)
{
    const int z = blockIdx.z;
    const float* A  = (z == 0) ? A0 : A1;
    const float* Bw = (z == 0) ? B0 : B1;
    float*       C  = (z == 0) ? C0 : C1;
    const int    M  = (z == 0) ? M0 : M1;
    if (blockIdx.y * 128 >= M) return;
    gemm_body(A, Bw, C, N, K, 0, K, epi, bias, resid);
}

__global__ __launch_bounds__(256, 2) void sgemm_splitk_k(
    const float* A, const float* Bw, float* Cpart, int M, int N, int K, int KC)
{
    const int z = blockIdx.z;
    gemm_body(A, Bw, Cpart + (size_t)z * M * N, N, K, z * KC, z * KC + KC,
              0, nullptr, nullptr);
}

// split-K reduce + epilogue (deterministic order)
__global__ void redk_k(const float* __restrict__ parts, int nparts, int total, int N,
                       int epi, const float* __restrict__ bias,
                       const float* __restrict__ resid, float* __restrict__ out)
{
    for (int idx = blockIdx.x * blockDim.x + threadIdx.x; idx < total;
         idx += gridDim.x * blockDim.x) {
        float s = parts[idx];
        for (int p = 1; p < nparts; p++) s += parts[(size_t)p * total + idx];
        const int c = idx % N;
        if (epi == 2) s += bias[c];
        else if (epi == 4) s += bias[c] + resid[idx];
        out[idx] = s;
    }
}

// ---------------------------------------------------------------------------
// Attention scores: out[bh,i,j] = scale * sum_d Q[b,i,h,d] * Kb[...,j,d]
// ---------------------------------------------------------------------------
__global__ __launch_bounds__(256, 3) void scores_k(
    const float* __restrict__ Q, const float* __restrict__ Kb,
    float* __restrict__ out, int L, int ldb, long bSB, long bSH, float scale)
{
    __shared__ __align__(16) float Qs[64][68];  // [d][i]
    __shared__ __align__(16) float Ks[64][68];  // [d][j]
    const int bh = blockIdx.z, b = bh >> 3, h = bh & 7;
    const int i0 = blockIdx.y * 64, j0 = blockIdx.x * 64;
    const float* Qg = Q + ((size_t)(b * SQ + i0)) * DM + h * DH;
    const float* Kg = Kb + (size_t)b * bSB + (size_t)h * bSH + (size_t)j0 * ldb;
    const int tid = threadIdx.x;
    const int rr = tid >> 4, c4 = (tid & 15) << 2;
#pragma unroll
    for (int s = 0; s < 4; s++) {
        const int r = rr + s * 16;
        float4 qv = *(const float4*)(Qg + (size_t)r * DM + c4);
        Qs[c4+0][r] = qv.x; Qs[c4+1][r] = qv.y; Qs[c4+2][r] = qv.z; Qs[c4+3][r] = qv.w;
        float4 kv2 = *(const float4*)(Kg + (size_t)r * ldb + c4);
        Ks[c4+0][r] = kv2.x; Ks[c4+1][r] = kv2.y; Ks[c4+2][r] = kv2.z; Ks[c4+3][r] = kv2.w;
    }
    __syncthreads();
    const int tx = tid & 15, ty = tid >> 4;
    unsigned long long acc[2][4];
#pragma unroll
    for (int m = 0; m < 2; m++)
#pragma unroll
        for (int n = 0; n < 4; n++) acc[m][n] = 0ull;
#pragma unroll
    for (int d = 0; d < 64; d++) {
        float4 av = *(const float4*)&Qs[d][ty*4];
        float4 bv = *(const float4*)&Ks[d][tx*4];
        unsigned long long am[2] = { pk2(av.x, av.y), pk2(av.z, av.w) };
        unsigned long long bd[4] = { pk2(bv.x, bv.x), pk2(bv.y, bv.y),
                                     pk2(bv.z, bv.z), pk2(bv.w, bv.w) };
#pragma unroll
        for (int m = 0; m < 2; m++)
#pragma unroll
            for (int n = 0; n < 4; n++) fma2(acc[m][n], am[m], bd[n]);
    }
    float* Og = out + ((long)bh * SQ + i0) * (long)L + j0 + tx * 4;
#pragma unroll
    for (int m2 = 0; m2 < 2; m2++) {
        float lo[4], hi[4];
#pragma unroll
        for (int n = 0; n < 4; n++) upk2(acc[m2][n], lo[n], hi[n]);
        *(float4*)(Og + (long)(ty*4 + 2*m2)     * L) =
            make_float4(lo[0]*scale, lo[1]*scale, lo[2]*scale, lo[3]*scale);
        *(float4*)(Og + (long)(ty*4 + 2*m2 + 1) * L) =
            make_float4(hi[0]*scale, hi[1]*scale, hi[2]*scale, hi[3]*scale);
    }
}

// ---------------------------------------------------------------------------
// AV: out[b,i,h,d] = sum_j P[bh,i,j] * V[b,j,h,d]
// ---------------------------------------------------------------------------
__global__ __launch_bounds__(256, 3) void av_k(
    const float* __restrict__ P, const float* __restrict__ V,
    float* __restrict__ out, int L)
{
    __shared__ __align__(16) float Ps[64][68];  // [j][i]
    __shared__ __align__(16) float Vs[64][68];  // [j][d]
    const int bh = blockIdx.z, b = bh >> 3, h = bh & 7;
    const int i0 = blockIdx.y * 64;
    const float* Pg = P + ((long)bh * SQ + i0) * (long)L;
    const float* Vg = V + (size_t)b * L * DM + h * DH;
    const int tid = threadIdx.x;
    const int rr = tid >> 4, c4 = (tid & 15) << 2;
    const int tx = tid & 15, ty = tid >> 4;
    unsigned long long acc[2][4];
#pragma unroll
    for (int m = 0; m < 2; m++)
#pragma unroll
        for (int n = 0; n < 4; n++) acc[m][n] = 0ull;
    for (int j0 = 0; j0 < L; j0 += 64) {
#pragma unroll
        for (int s = 0; s < 4; s++) {
            const int r = rr + s * 16;
            float4 pv = *(const float4*)(Pg + (long)r * L + j0 + c4);
            Ps[c4+0][r] = pv.x; Ps[c4+1][r] = pv.y; Ps[c4+2][r] = pv.z; Ps[c4+3][r] = pv.w;
            float4 vv = *(const float4*)(Vg + (size_t)(j0 + r) * DM + c4);
            *(float4*)&Vs[r][c4] = vv;
        }
        __syncthreads();
#pragma unroll
        for (int j = 0; j < 64; j++) {
            float4 av = *(const float4*)&Ps[j][ty*4];
            float4 bv = *(const float4*)&Vs[j][tx*4];
            unsigned long long am[2] = { pk2(av.x, av.y), pk2(av.z, av.w) };
            unsigned long long bd[4] = { pk2(bv.x, bv.x), pk2(bv.y, bv.y),
                                         pk2(bv.z, bv.z), pk2(bv.w, bv.w) };
#pragma unroll
            for (int m = 0; m < 2; m++)
#pragma unroll
                for (int n = 0; n < 4; n++) fma2(acc[m][n], am[m], bd[n]);
        }
        __syncthreads();
    }
    float* Og = out + ((size_t)(b * SQ + i0)) * DM + h * DH + tx * 4;
#pragma unroll
    for (int m2 = 0; m2 < 2; m2++) {
        float lo[4], hi[4];
#pragma unroll
        for (int n = 0; n < 4; n++) upk2(acc[m2][n], lo[n], hi[n]);
        *(float4*)(Og + (size_t)(ty*4 + 2*m2)     * DM) = make_float4(lo[0], lo[1], lo[2], lo[3]);
        *(float4*)(Og + (size_t)(ty*4 + 2*m2 + 1) * DM) = make_float4(hi[0], hi[1], hi[2], hi[3]);
    }
}

// ---------------------------------------------------------------------------
// Softmax over row of length L (multiple of 128), optional shifted pos add
// ---------------------------------------------------------------------------
__global__ __launch_bounds__(128) void softmax_k(
    float* __restrict__ dots, const float* __restrict__ posR, int L, int usePos)
{
    const int i = blockIdx.x, bh = blockIdx.y;
    float* row = dots + ((long)bh * SQ + i) * (long)L;
    const float* prow = posR + ((long)bh * SQ + i) * (long)KVN;
    const int tid = threadIdx.x;
    const int nper = L >> 7;
    float vals[9];
    float mx = -1e30f;
    for (int t = 0; t < nper; t++) {
        const int j = tid + t * 128;
        float vv = row[j];
        if (usePos) {
            const int jp = j + (SQ - 1) - i;
            if (jp < KVN) vv += prow[jp];
        }
        vals[t] = vv;
        mx = fmaxf(mx, vv);
    }
    __shared__ float sh[128];
    sh[tid] = mx; __syncthreads();
    for (int o = 64; o > 0; o >>= 1) { if (tid < o) sh[tid] = fmaxf(sh[tid], sh[tid + o]); __syncthreads(); }
    mx = sh[0]; __syncthreads();
    float s = 0.f;
    for (int t = 0; t < nper; t++) { vals[t] = __expf(vals[t] - mx); s += vals[t]; }
    sh[tid] = s; __syncthreads();
    for (int o = 64; o > 0; o >>= 1) { if (tid < o) sh[tid] += sh[tid + o]; __syncthreads(); }
    const float inv = 1.0f / sh[0];
    for (int t = 0; t < nper; t++) row[tid + t * 128] = vals[t] * inv;
}

// ---------------------------------------------------------------------------
// LayerNorm over D=512
// ---------------------------------------------------------------------------
__global__ __launch_bounds__(128) void ln_k(
    const float* __restrict__ x, const float* __restrict__ g,
    const float* __restrict__ bt, float* __restrict__ out)
{
    const int row = blockIdx.x, tid = threadIdx.x;
    const float* xr = x + (size_t)row * DM;
    float v[4]; float s = 0.f, s2 = 0.f;
#pragma unroll
    for (int t = 0; t < 4; t++) { v[t] = xr[tid + t * 128]; s += v[t]; s2 += v[t] * v[t]; }
    __shared__ float sa[128], sb[128];
    sa[tid] = s; sb[tid] = s2; __syncthreads();
    for (int o = 64; o > 0; o >>= 1) { if (tid < o) { sa[tid] += sa[tid+o]; sb[tid] += sb[tid+o]; } __syncthreads(); }
    const float mean = sa[0] * (1.0f / DM);
    const float var  = sb[0] * (1.0f / DM) - mean * mean;
    const float rs   = rsqrtf(var + 1e-5f);
    float* orow = out + (size_t)row * DM;
#pragma unroll
    for (int t = 0; t < 4; t++) {
        const int c = tid + t * 128;
        orow[c] = (v[t] - mean) * rs * g[c] + bt[c];
    }
}

// ---------------------------------------------------------------------------
// Misc kernels
// ---------------------------------------------------------------------------
__global__ void embed_k(const int* __restrict__ trg, const float* __restrict__ emb,
                        float* __restrict__ x)
{
    const int total = MROWS * (DM / 4);
    for (int idx = blockIdx.x * blockDim.x + threadIdx.x; idx < total; idx += gridDim.x * blockDim.x) {
        const int row = idx >> 7, c = idx & 127;
        ((float4*)x)[idx] = ((const float4*)emb)[(size_t)trg[row] * 128 + c];
    }
}

__global__ void kvbuild_k(const float* __restrict__ cm, const float* __restrict__ mem,
                          const float* __restrict__ x, float* __restrict__ kv)
{
    const int row = blockIdx.x;
    const int b = row / KVN, p = row % KVN;
    const float* src;
    if (p < CMEMN)             src = cm  + ((size_t)b * CMEMN + p) * DM;
    else if (p < CMEMN + MEMN) src = mem + ((size_t)b * MEMN + (p - CMEMN)) * DM;
    else                       src = x   + ((size_t)b * SQ + (p - CMEMN - MEMN)) * DM;
    ((float4*)(kv + (size_t)row * DM))[threadIdx.x] = ((const float4*)src)[threadIdx.x];
}

// transpose conv_w (NL, o, d, r) -> wc[layer][k=r*512+d][o]
__global__ void convwT_k(const float* __restrict__ cw, float* __restrict__ wc)
{
    const int total = NLAYERS * RRATIO * DM * DM;
    for (int idx = blockIdx.x * blockDim.x + threadIdx.x; idx < total; idx += gridDim.x * blockDim.x) {
        const int layer = idx / (RRATIO * DM * DM);
        const int rem   = idx % (RRATIO * DM * DM);
        const int k = rem / DM, o = rem % DM;
        wc[idx] = cw[(size_t)layer * RRATIO * DM * DM + (size_t)o * (RRATIO * DM) + (k & 511) * 4 + (k >> 9)];
    }
}

__global__ __launch_bounds__(256) void mse_k(const float* __restrict__ a,
                                             const float* __restrict__ b,
                                             float* __restrict__ part)
{
    __shared__ float sh[256];
    float s = 0.f;
    for (int idx = blockIdx.x * 256 + threadIdx.x; idx < MROWS * DM; idx += 128 * 256) {
        const float d = a[idx] - b[idx];
        s += d * d;
    }
    sh[threadIdx.x] = s; __syncthreads();
    for (int o = 128; o > 0; o >>= 1) { if (threadIdx.x < o) sh[threadIdx.x] += sh[threadIdx.x + o]; __syncthreads(); }
    if (threadIdx.x == 0) part[blockIdx.x] = sh[0];
}

__global__ void copyout_k(const float* __restrict__ x, float* __restrict__ out)
{
    const int total = MROWS * (DM / 4);
    for (int idx = blockIdx.x * blockDim.x + threadIdx.x; idx < total; idx += gridDim.x * blockDim.x)
        ((float4*)out)[idx] = ((const float4*)x)[idx];
}

__global__ __launch_bounds__(128) void loss_k(const float* __restrict__ part,
                                              float* __restrict__ out, int out_size)
{
    __shared__ float sh[128];
    float s = 0.f;
    for (int j = threadIdx.x; j < NLAYERS * 128; j += 128) s += part[j];
    sh[threadIdx.x] = s; __syncthreads();
    for (int o = 64; o > 0; o >>= 1) { if (threadIdx.x < o) sh[threadIdx.x] += sh[threadIdx.x + o]; __syncthreads(); }
    if (threadIdx.x == 0 && out_size > MROWS * DM)
        out[MROWS * DM] = sh[0] * (1.0f / ((float)(MROWS * DM) * (float)NLAYERS));
}

// ---------------------------------------------------------------------------
// Host driver
// ---------------------------------------------------------------------------
extern "C" void kernel_launch(void* const* d_in, const int* in_sizes, int n_in,
                              void* d_out, int out_size)
{
    (void)in_sizes; (void)n_in;
    const int*   trg     = (const int*)  d_in[0];
    const float* latent  = (const float*)d_in[3];
    const float* mems    = (const float*)d_in[4];
    const float* cmems   = (const float*)d_in[5];
    const float* pos_emb = (const float*)d_in[6];
    const float* embed   = (const float*)d_in[7];
    const float* W_self  = (const float*)d_in[8];
    const float* ln1_g   = (const float*)d_in[9];
    const float* ln1_b   = (const float*)d_in[10];
    const float* conv_w  = (const float*)d_in[11];
    const float* conv_b  = (const float*)d_in[12];
    const float* W_src   = (const float*)d_in[13];
    const float* ln2_g   = (const float*)d_in[14];
    const float* ln2_b   = (const float*)d_in[15];
    const float* w1      = (const float*)d_in[16];
    const float* b1      = (const float*)d_in[17];
    const float* w2      = (const float*)d_in[18];
    const float* b2      = (const float*)d_in[19];

    float *x,*kv,*q,*k,*v,*dots,*pos,*ao,*t1,*t2,*cm,*kcm,*vcm,*y,*ff,*wc,*sk,*part;
    cudaGetSymbolAddress((void**)&x,   g_x);
    cudaGetSymbolAddress((void**)&kv,  g_kv);
    cudaGetSymbolAddress((void**)&q,   g_q);
    cudaGetSymbolAddress((void**)&k,   g_k);
    cudaGetSymbolAddress((void**)&v,   g_v);
    cudaGetSymbolAddress((void**)&dots,g_dots);
    cudaGetSymbolAddress((void**)&pos, g_pos);
    cudaGetSymbolAddress((void**)&ao,  g_ao);
    cudaGetSymbolAddress((void**)&t1,  g_t1);
    cudaGetSymbolAddress((void**)&t2,  g_t2);
    cudaGetSymbolAddress((void**)&cm,  g_cm);
    cudaGetSymbolAddress((void**)&kcm, g_kcm);
    cudaGetSymbolAddress((void**)&vcm, g_vcm);
    cudaGetSymbolAddress((void**)&y,   g_y);
    cudaGetSymbolAddress((void**)&ff,  g_ff);
    cudaGetSymbolAddress((void**)&wc,  g_wc);
    cudaGetSymbolAddress((void**)&sk,  g_sk);
    cudaGetSymbolAddress((void**)&part,g_part);

    // opt-in to 49.7 KB dynamic smem for the big GEMMs (host-side, capture-safe)
    cudaFuncSetAttribute(sgemm_big_t<0>, cudaFuncAttributeMaxDynamicSharedMemorySize, SMEM_BIG);
    cudaFuncSetAttribute(sgemm_big_t<3>, cudaFuncAttributeMaxDynamicSharedMemorySize, SMEM_BIG);
    cudaFuncSetAttribute(sgemm_big_splitk, cudaFuncAttributeMaxDynamicSharedMemorySize, SMEM_BIG);

    embed_k<<<256, 256>>>(trg, embed, x);
    convwT_k<<<2048, 256>>>(conv_w, wc);

    for (int i = 0; i < NLAYERS; i++) {
        const float* Wq  = W_self + ((size_t)i * 4 + 0) * DM * DM;
        const float* Wk  = W_self + ((size_t)i * 4 + 1) * DM * DM;
        const float* Wv  = W_self + ((size_t)i * 4 + 2) * DM * DM;
        const float* Wo  = W_self + ((size_t)i * 4 + 3) * DM * DM;
        const float* Wq2 = W_src  + ((size_t)i * 4 + 0) * DM * DM;
        const float* Wk2 = W_src  + ((size_t)i * 4 + 1) * DM * DM;
        const float* Wv2 = W_src  + ((size_t)i * 4 + 2) * DM * DM;
        const float* Wo2 = W_src  + ((size_t)i * 4 + 3) * DM * DM;
        const float* mems_i  = mems  + (size_t)i * NB * MEMN * DM;
        const float* cmems_i = cmems + (size_t)i * NB * CMEMN * DM;

        // ---- self attention (batched q/k/v projection, big tiles) ----
        kvbuild_k<<<NB * KVN, 128>>>(cmems_i, mems_i, x, kv);
        sgemm_big_t<0><<<dim3(4, 36, 3), 256, SMEM_BIG>>>(
            x,  Wq, q, MROWS,
            kv, Wk, k, NB * KVN,
            kv, Wv, v, NB * KVN,
            DM, DM, nullptr);
        scores_k<<<dim3(18, 8, 32), 256>>>(q, k,       dots, KVN, DM, (long)KVN * DM, 64,             0.125f);
        scores_k<<<dim3(18, 8, 32), 256>>>(q, pos_emb, pos,  KVN, DH, 0,              (long)KVN * DH, 8.0f);
        softmax_k<<<dim3(SQ, 32), 128>>>(dots, pos, KVN, 1);
        av_k<<<dim3(1, 8, 32), 256>>>(dots, v, ao, KVN);
        sgemm_k<<<dim3(8, 16, 1), 256>>>(ao, Wo, y, MROWS,
                                         nullptr, nullptr, nullptr, 0,
                                         DM, DM, 1, nullptr, x);
        ln_k<<<MROWS, 128>>>(y, ln1_g + i * DM, ln1_b + i * DM, x);

        // ---- conv compress (GEMM, split-K=4) ----
        sgemm_splitk_k<<<dim3(8, 4, 4), 256>>>(mems_i, wc + (size_t)i * RRATIO * DM * DM,
                                               sk, NB * CMEMN, DM, RRATIO * DM, DM);
        redk_k<<<256, 256>>>(sk, 4, NB * CMEMN * DM, DM, 2, conv_b + i * DM, nullptr, cm);

        // ---- reconstruction attention loss (batched q/k/v, big tiles) ----
        sgemm_big_t<0><<<dim3(4, 16, 3), 256, SMEM_BIG>>>(
            x,      Wq, q, MROWS,
            mems_i, Wk, k, MROWS,
            mems_i, Wv, v, MROWS,
            DM, DM, nullptr);
        scores_k<<<dim3(8, 8, 32), 256>>>(q, k, dots, MEMN, DM, (long)MEMN * DM, 64, 0.125f);
        softmax_k<<<dim3(SQ, 32), 128>>>(dots, pos, MEMN, 0);
        av_k<<<dim3(1, 8, 32), 256>>>(dots, v, t1, MEMN);
        sgemm_k<<<dim3(8, 4, 2), 256>>>(cm, Wk, kcm, NB * CMEMN,
                                        cm, Wv, vcm, NB * CMEMN,
                                        DM, DM, 0, nullptr, nullptr);
        scores_k<<<dim3(2, 8, 32), 256>>>(q, kcm, dots, CMEMN, DM, (long)CMEMN * DM, 64, 0.125f);
        softmax_k<<<dim3(SQ, 32), 128>>>(dots, pos, CMEMN, 0);
        av_k<<<dim3(1, 8, 32), 256>>>(dots, vcm, t2, CMEMN);
        mse_k<<<128, 256>>>(t1, t2, part + i * 128);

        // ---- cross attention to latent (batched q/k/v, big tiles) ----
        sgemm_big_t<0><<<dim3(4, 16, 3), 256, SMEM_BIG>>>(
            x,      Wq2, q, MROWS,
            latent, Wk2, k, NB * LLAT,
            latent, Wv2, v, NB * LLAT,
            DM, DM, nullptr);
        scores_k<<<dim3(4, 8, 32), 256>>>(q, k, dots, LLAT, DM, (long)LLAT * DM, 64, 0.125f);
        softmax_k<<<dim3(SQ, 32), 128>>>(dots, pos, LLAT, 0);
        av_k<<<dim3(1, 8, 32), 256>>>(dots, v, ao, LLAT);
        sgemm_k<<<dim3(8, 16, 1), 256>>>(ao, Wo2, x, MROWS,
                                         nullptr, nullptr, nullptr, 0,
                                         DM, DM, 0, nullptr, nullptr);

        // ---- feed-forward ----
        ln_k<<<MROWS, 128>>>(x, ln2_g + i * DM, ln2_b + i * DM, y);
        sgemm_big_t<3><<<dim3(16, 16, 1), 256, SMEM_BIG>>>(
            y, w1 + (size_t)i * DM * FFD, ff, MROWS,
            nullptr, nullptr, nullptr, 0,
            nullptr, nullptr, nullptr, 0,
            FFD, DM, b1 + (size_t)i * FFD);
        sgemm_big_splitk<<<dim3(4, 16, 2), 256, SMEM_BIG>>>(
            ff, w2 + (size_t)i * FFD * DM, sk, MROWS, DM, FFD, FFD / 2);
        redk_k<<<512, 256>>>(sk, 2, MROWS * DM, DM, 4, b2 + i * DM, x, x);
    }

    copyout_k<<<512, 256>>>(x, (float*)d_out);
    loss_k<<<1, 128>>>(part, (float*)d_out, out_size);
}

// round 9
// speedup vs baseline: 1.0162x; 1.0162x over previous
#include <cuda_runtime.h>
#include <math.h>
#include <stdint.h>

// ---------------------------------------------------------------------------
// Problem constants
// ---------------------------------------------------------------------------
#define NLAYERS 4
#define NB      4
#define SQ      512
#define DM      512
#define NH      8
#define DH      64
#define MEMN    512
#define CMEMN   128
#define RRATIO  4
#define LLAT    256
#define FFD     2048
#define KVN     (CMEMN + MEMN + SQ)   // 1152
#define MROWS   (NB * SQ)             // 2048

// ---------------------------------------------------------------------------
// Scratch (device globals)
// ---------------------------------------------------------------------------
__device__ float g_x  [MROWS * DM];
__device__ float g_kv [NB * KVN * DM];
__device__ float g_q  [MROWS * DM];
__device__ float g_k  [NB * KVN * DM];
__device__ float g_v  [NB * KVN * DM];
__device__ float g_dots[(size_t)NB * NH * SQ * KVN];
__device__ float g_pos [(size_t)NB * NH * SQ * KVN];
__device__ float g_ao [MROWS * DM];
__device__ float g_t1 [MROWS * DM];
__device__ float g_t2 [MROWS * DM];
__device__ float g_cm [NB * CMEMN * DM];
__device__ float g_kcm[NB * CMEMN * DM];
__device__ float g_vcm[NB * CMEMN * DM];
__device__ float g_y  [MROWS * DM];
__device__ float g_ff [MROWS * FFD];
__device__ float g_wc [NLAYERS * RRATIO * DM * DM];
__device__ float g_sk [4 * 1024 * 1024];          // split-K partials
__device__ float g_part[NLAYERS * 128];

// ---------------------------------------------------------------------------
// Packed fp32x2 helpers (Blackwell FFMA2)
// ---------------------------------------------------------------------------
__device__ __forceinline__ unsigned long long pk2(float lo, float hi) {
    unsigned long long r;
    asm("mov.b64 %0, {%1,%2};" : "=l"(r) : "f"(lo), "f"(hi));
    return r;
}
__device__ __forceinline__ void upk2(unsigned long long v, float& lo, float& hi) {
    asm("mov.b64 {%0,%1}, %2;" : "=f"(lo), "=f"(hi) : "l"(v));
}
__device__ __forceinline__ void fma2(unsigned long long& d, unsigned long long a,
                                     unsigned long long b) {
    asm("fma.rn.f32x2 %0, %1, %2, %0;" : "+l"(d) : "l"(a), "l"(b));
}

// ===========================================================================
// SGEMM: BM=128, BN=64, BK=16, 256 threads, 8x4 outputs/thread.
// A smem [k][m] floats, read directly as u64 m-pairs (no packing movs).
// B smem pre-duplicated (b,b) u64, strided col map c = col0 + tx + 16n
//   -> conflict-free broadcast LDS.64, zero duplication movs.
// Inner loop per k-step: 8 x LDS.64 + 16 x fma2, nothing else.
// epi: 0 none, 1 +resid, 2 +bias, 3 gelu(.+bias), 4 +bias+resid
// ===========================================================================
__device__ __forceinline__ void gemm_body(
    const float* __restrict__ A, const float* __restrict__ Bw, float* __restrict__ C,
    int N, int K, int kBeg, int kEnd,
    int epi, const float* __restrict__ bias, const float* __restrict__ resid)
{
    __shared__ __align__(16) float As[2][16][132];
    __shared__ unsigned long long Bs[2][16][64];
    const int tid  = threadIdx.x;
    const int tx   = tid & 15, ty = tid >> 4;
    const int row0 = blockIdx.y * 128, col0 = blockIdx.x * 64;
    const int ar   = tid >> 2,  ak = (tid & 3) << 2;   // A fill
    const int br   = tid >> 4,  bc = tid & 15;         // B fill (strided cols)
    const float* Ag = A + (size_t)row0 * K + kBeg;
    const float* Bg = Bw + (size_t)kBeg * N + col0;

    unsigned long long acc[4][4];
#pragma unroll
    for (int m = 0; m < 4; m++)
#pragma unroll
        for (int n = 0; n < 4; n++) acc[m][n] = 0ull;

    const int nk = (kEnd - kBeg) >> 4;

    // preload tile 0
    float4 a0 = *(const float4*)(Ag + (size_t)ar        * K + ak);
    float4 a1 = *(const float4*)(Ag + (size_t)(ar + 64) * K + ak);
    float bp[4];
#pragma unroll
    for (int n = 0; n < 4; n++) bp[n] = Bg[(size_t)br * N + bc + 16 * n];
    As[0][ak+0][ar]    = a0.x; As[0][ak+1][ar]    = a0.y; As[0][ak+2][ar]    = a0.z; As[0][ak+3][ar]    = a0.w;
    As[0][ak+0][ar+64] = a1.x; As[0][ak+1][ar+64] = a1.y; As[0][ak+2][ar+64] = a1.z; As[0][ak+3][ar+64] = a1.w;
#pragma unroll
    for (int n = 0; n < 4; n++) Bs[0][br][bc + 16 * n] = pk2(bp[n], bp[n]);
    __syncthreads();

    int buf = 0;
    for (int t = 0; t < nk; t++) {
        const bool more = (t + 1 < nk);
        if (more) {
            const float* Ag2 = Ag + (t + 1) * 16;
            a0 = *(const float4*)(Ag2 + (size_t)ar        * K + ak);
            a1 = *(const float4*)(Ag2 + (size_t)(ar + 64) * K + ak);
            const float* Bg2 = Bg + (size_t)((t + 1) * 16) * N;
#pragma unroll
            for (int n = 0; n < 4; n++) bp[n] = Bg2[(size_t)br * N + bc + 16 * n];
        }
        const unsigned long long* Ap =
            (const unsigned long long*)(&As[buf][0][0]) + ty * 4;   // row stride 66 u64
        const unsigned long long* Bp = &Bs[buf][0][tx];
#pragma unroll
        for (int k = 0; k < 16; k++) {
            unsigned long long am0 = Ap[k*66 + 0];
            unsigned long long am1 = Ap[k*66 + 1];
            unsigned long long am2 = Ap[k*66 + 2];
            unsigned long long am3 = Ap[k*66 + 3];
#pragma unroll
            for (int n = 0; n < 4; n++) {
                unsigned long long bd = Bp[k*64 + 16*n];
                fma2(acc[0][n], am0, bd);
                fma2(acc[1][n], am1, bd);
                fma2(acc[2][n], am2, bd);
                fma2(acc[3][n], am3, bd);
            }
        }
        if (more) {
            const int nb = buf ^ 1;
            As[nb][ak+0][ar]    = a0.x; As[nb][ak+1][ar]    = a0.y; As[nb][ak+2][ar]    = a0.z; As[nb][ak+3][ar]    = a0.w;
            As[nb][ak+0][ar+64] = a1.x; As[nb][ak+1][ar+64] = a1.y; As[nb][ak+2][ar+64] = a1.z; As[nb][ak+3][ar+64] = a1.w;
#pragma unroll
            for (int n = 0; n < 4; n++) Bs[nb][br][bc + 16 * n] = pk2(bp[n], bp[n]);
        }
        __syncthreads();
        buf ^= 1;
    }

    // epilogue: rows row0+ty*8+2m+{0,1}, cols col0+tx+16n
#pragma unroll
    for (int m = 0; m < 4; m++) {
        const int r = row0 + ty * 8 + 2 * m;
#pragma unroll
        for (int n = 0; n < 4; n++) {
            const int c = col0 + tx + 16 * n;
            float lo, hi;
            upk2(acc[m][n], lo, hi);
            if (epi >= 2) { const float bb = bias[c]; lo += bb; hi += bb; }
            if (epi == 3) {
                lo = 0.5f * lo * (1.0f + erff(lo * 0.70710678118654752440f));
                hi = 0.5f * hi * (1.0f + erff(hi * 0.70710678118654752440f));
            }
            if (epi == 1 || epi == 4) {
                lo += resid[(size_t)r       * N + c];
                hi += resid[(size_t)(r + 1) * N + c];
            }
            C[(size_t)r       * N + c] = lo;
            C[(size_t)(r + 1) * N + c] = hi;
        }
    }
}

// z-batched SGEMM (up to 3 problems sharing N, K; early-exit past M_z)
__global__ __launch_bounds__(256, 2) void sgemm_k(
    const float* A0, const float* B0, float* C0, int M0,
    const float* A1, const float* B1, float* C1, int M1,
    const float* A2, const float* B2, float* C2, int M2,
    int N, int K, int epi, const float* bias, const float* resid)
{
    const int z = blockIdx.z;
    const float* A  = (z == 0) ? A0 : (z == 1) ? A1 : A2;
    const float* Bw = (z == 0) ? B0 : (z == 1) ? B1 : B2;
    float*       C  = (z == 0) ? C0 : (z == 1) ? C1 : C2;
    const int    M  = (z == 0) ? M0 : (z == 1) ? M1 : M2;
    if (blockIdx.y * 128 >= M) return;
    gemm_body(A, Bw, C, N, K, 0, K, epi, bias, resid);
}

// split-K SGEMM: z = K-chunk, writes partials Cpart[z][M][N]
__global__ __launch_bounds__(256, 2) void sgemm_splitk_k(
    const float* A, const float* Bw, float* Cpart, int M, int N, int K, int KC)
{
    const int z = blockIdx.z;
    gemm_body(A, Bw, Cpart + (size_t)z * M * N, N, K, z * KC, z * KC + KC,
              0, nullptr, nullptr);
}

// split-K reduce + epilogue (deterministic order)
__global__ void redk_k(const float* __restrict__ parts, int nparts, int total, int N,
                       int epi, const float* __restrict__ bias,
                       const float* __restrict__ resid, float* __restrict__ out)
{
    for (int idx = blockIdx.x * blockDim.x + threadIdx.x; idx < total;
         idx += gridDim.x * blockDim.x) {
        float s = parts[idx];
        for (int p = 1; p < nparts; p++) s += parts[(size_t)p * total + idx];
        const int c = idx % N;
        if (epi == 2) s += bias[c];
        else if (epi == 4) s += bias[c] + resid[idx];
        out[idx] = s;
    }
}

// ---------------------------------------------------------------------------
// Attention scores: out[bh,i,j] = scale * sum_d Q[b,i,h,d] * Kb[...,j,d]
// shiftSkip=1: skip blocks never read through the shift() gather (pos scores)
// ---------------------------------------------------------------------------
__global__ __launch_bounds__(256, 3) void scores_k(
    const float* __restrict__ Q, const float* __restrict__ Kb,
    float* __restrict__ out, int L, int ldb, long bSB, long bSH, float scale,
    int shiftSkip)
{
    const int i0 = blockIdx.y * 64, j0 = blockIdx.x * 64;
    if (shiftSkip && (i0 + j0 <= 384)) return;
    __shared__ __align__(16) float Qs[64][68];  // [d][i]
    __shared__ __align__(16) float Ks[64][68];  // [d][j]
    const int bh = blockIdx.z, b = bh >> 3, h = bh & 7;
    const float* Qg = Q + ((size_t)(b * SQ + i0)) * DM + h * DH;
    const float* Kg = Kb + (size_t)b * bSB + (size_t)h * bSH + (size_t)j0 * ldb;
    const int tid = threadIdx.x;
    const int rr = tid >> 4, c4 = (tid & 15) << 2;
#pragma unroll
    for (int s = 0; s < 4; s++) {
        const int r = rr + s * 16;
        float4 qv = *(const float4*)(Qg + (size_t)r * DM + c4);
        Qs[c4+0][r] = qv.x; Qs[c4+1][r] = qv.y; Qs[c4+2][r] = qv.z; Qs[c4+3][r] = qv.w;
        float4 kv2 = *(const float4*)(Kg + (size_t)r * ldb + c4);
        Ks[c4+0][r] = kv2.x; Ks[c4+1][r] = kv2.y; Ks[c4+2][r] = kv2.z; Ks[c4+3][r] = kv2.w;
    }
    __syncthreads();
    const int tx = tid & 15, ty = tid >> 4;
    unsigned long long acc[2][4];
#pragma unroll
    for (int m = 0; m < 2; m++)
#pragma unroll
        for (int n = 0; n < 4; n++) acc[m][n] = 0ull;
#pragma unroll
    for (int d = 0; d < 64; d++) {
        float4 av = *(const float4*)&Qs[d][ty*4];
        float4 bv = *(const float4*)&Ks[d][tx*4];
        unsigned long long am[2] = { pk2(av.x, av.y), pk2(av.z, av.w) };
        unsigned long long bd[4] = { pk2(bv.x, bv.x), pk2(bv.y, bv.y),
                                     pk2(bv.z, bv.z), pk2(bv.w, bv.w) };
#pragma unroll
        for (int m = 0; m < 2; m++)
#pragma unroll
            for (int n = 0; n < 4; n++) fma2(acc[m][n], am[m], bd[n]);
    }
    float* Og = out + ((long)bh * SQ + i0) * (long)L + j0 + tx * 4;
#pragma unroll
    for (int m2 = 0; m2 < 2; m2++) {
        float lo[4], hi[4];
#pragma unroll
        for (int n = 0; n < 4; n++) upk2(acc[m2][n], lo[n], hi[n]);
        *(float4*)(Og + (long)(ty*4 + 2*m2)     * L) =
            make_float4(lo[0]*scale, lo[1]*scale, lo[2]*scale, lo[3]*scale);
        *(float4*)(Og + (long)(ty*4 + 2*m2 + 1) * L) =
            make_float4(hi[0]*scale, hi[1]*scale, hi[2]*scale, hi[3]*scale);
    }
}

// ---------------------------------------------------------------------------
// AV: out[b,i,h,d] = sum_j P[bh,i,j] * V[b,j,h,d]
// ---------------------------------------------------------------------------
__global__ __launch_bounds__(256, 3) void av_k(
    const float* __restrict__ P, const float* __restrict__ V,
    float* __restrict__ out, int L)
{
    __shared__ __align__(16) float Ps[64][68];  // [j][i]
    __shared__ __align__(16) float Vs[64][68];  // [j][d]
    const int bh = blockIdx.z, b = bh >> 3, h = bh & 7;
    const int i0 = blockIdx.y * 64;
    const float* Pg = P + ((long)bh * SQ + i0) * (long)L;
    const float* Vg = V + (size_t)b * L * DM + h * DH;
    const int tid = threadIdx.x;
    const int rr = tid >> 4, c4 = (tid & 15) << 2;
    const int tx = tid & 15, ty = tid >> 4;
    unsigned long long acc[2][4];
#pragma unroll
    for (int m = 0; m < 2; m++)
#pragma unroll
        for (int n = 0; n < 4; n++) acc[m][n] = 0ull;
    for (int j0 = 0; j0 < L; j0 += 64) {
#pragma unroll
        for (int s = 0; s < 4; s++) {
            const int r = rr + s * 16;
            float4 pv = *(const float4*)(Pg + (long)r * L + j0 + c4);
            Ps[c4+0][r] = pv.x; Ps[c4+1][r] = pv.y; Ps[c4+2][r] = pv.z; Ps[c4+3][r] = pv.w;
            float4 vv = *(const float4*)(Vg + (size_t)(j0 + r) * DM + c4);
            *(float4*)&Vs[r][c4] = vv;
        }
        __syncthreads();
#pragma unroll
        for (int j = 0; j < 64; j++) {
            float4 av = *(const float4*)&Ps[j][ty*4];
            float4 bv = *(const float4*)&Vs[j][tx*4];
            unsigned long long am[2] = { pk2(av.x, av.y), pk2(av.z, av.w) };
            unsigned long long bd[4] = { pk2(bv.x, bv.x), pk2(bv.y, bv.y),
                                         pk2(bv.z, bv.z), pk2(bv.w, bv.w) };
#pragma unroll
            for (int m = 0; m < 2; m++)
#pragma unroll
                for (int n = 0; n < 4; n++) fma2(acc[m][n], am[m], bd[n]);
        }
        __syncthreads();
    }
    float* Og = out + ((size_t)(b * SQ + i0)) * DM + h * DH + tx * 4;
#pragma unroll
    for (int m2 = 0; m2 < 2; m2++) {
        float lo[4], hi[4];
#pragma unroll
        for (int n = 0; n < 4; n++) upk2(acc[m2][n], lo[n], hi[n]);
        *(float4*)(Og + (size_t)(ty*4 + 2*m2)     * DM) = make_float4(lo[0], lo[1], lo[2], lo[3]);
        *(float4*)(Og + (size_t)(ty*4 + 2*m2 + 1) * DM) = make_float4(hi[0], hi[1], hi[2], hi[3]);
    }
}

// ---------------------------------------------------------------------------
// Softmax over row of length L (multiple of 128), optional shifted pos add
// ---------------------------------------------------------------------------
__global__ __launch_bounds__(128) void softmax_k(
    float* __restrict__ dots, const float* __restrict__ posR, int L, int usePos)
{
    const int i = blockIdx.x, bh = blockIdx.y;
    float* row = dots + ((long)bh * SQ + i) * (long)L;
    const float* prow = posR + ((long)bh * SQ + i) * (long)KVN;
    const int tid = threadIdx.x;
    const int nper = L >> 7;
    float vals[9];
    float mx = -1e30f;
    for (int t = 0; t < nper; t++) {
        const int j = tid + t * 128;
        float vv = row[j];
        if (usePos) {
            const int jp = j + (SQ - 1) - i;
            if (jp < KVN) vv += prow[jp];
        }
        vals[t] = vv;
        mx = fmaxf(mx, vv);
    }
    __shared__ float sh[128];
    sh[tid] = mx; __syncthreads();
    for (int o = 64; o > 0; o >>= 1) { if (tid < o) sh[tid] = fmaxf(sh[tid], sh[tid + o]); __syncthreads(); }
    mx = sh[0]; __syncthreads();
    float s = 0.f;
    for (int t = 0; t < nper; t++) { vals[t] = __expf(vals[t] - mx); s += vals[t]; }
    sh[tid] = s; __syncthreads();
    for (int o = 64; o > 0; o >>= 1) { if (tid < o) sh[tid] += sh[tid + o]; __syncthreads(); }
    const float inv = 1.0f / sh[0];
    for (int t = 0; t < nper; t++) row[tid + t * 128] = vals[t] * inv;
}

// ---------------------------------------------------------------------------
// LayerNorm over D=512
// ---------------------------------------------------------------------------
__global__ __launch_bounds__(128) void ln_k(
    const float* __restrict__ x, const float* __restrict__ g,
    const float* __restrict__ bt, float* __restrict__ out)
{
    const int row = blockIdx.x, tid = threadIdx.x;
    const float* xr = x + (size_t)row * DM;
    float v[4]; float s = 0.f, s2 = 0.f;
#pragma unroll
    for (int t = 0; t < 4; t++) { v[t] = xr[tid + t * 128]; s += v[t]; s2 += v[t] * v[t]; }
    __shared__ float sa[128], sb[128];
    sa[tid] = s; sb[tid] = s2; __syncthreads();
    for (int o = 64; o > 0; o >>= 1) { if (tid < o) { sa[tid] += sa[tid+o]; sb[tid] += sb[tid+o]; } __syncthreads(); }
    const float mean = sa[0] * (1.0f / DM);
    const float var  = sb[0] * (1.0f / DM) - mean * mean;
    const float rs   = rsqrtf(var + 1e-5f);
    float* orow = out + (size_t)row * DM;
#pragma unroll
    for (int t = 0; t < 4; t++) {
        const int c = tid + t * 128;
        orow[c] = (v[t] - mean) * rs * g[c] + bt[c];
    }
}

// ---------------------------------------------------------------------------
// Misc kernels
// ---------------------------------------------------------------------------
__global__ void embed_k(const int* __restrict__ trg, const float* __restrict__ emb,
                        float* __restrict__ x)
{
    const int total = MROWS * (DM / 4);
    for (int idx = blockIdx.x * blockDim.x + threadIdx.x; idx < total; idx += gridDim.x * blockDim.x) {
        const int row = idx >> 7, c = idx & 127;
        ((float4*)x)[idx] = ((const float4*)emb)[(size_t)trg[row] * 128 + c];
    }
}

__global__ void kvbuild_k(const float* __restrict__ cm, const float* __restrict__ mem,
                          const float* __restrict__ x, float* __restrict__ kv)
{
    const int row = blockIdx.x;
    const int b = row / KVN, p = row % KVN;
    const float* src;
    if (p < CMEMN)             src = cm  + ((size_t)b * CMEMN + p) * DM;
    else if (p < CMEMN + MEMN) src = mem + ((size_t)b * MEMN + (p - CMEMN)) * DM;
    else                       src = x   + ((size_t)b * SQ + (p - CMEMN - MEMN)) * DM;
    ((float4*)(kv + (size_t)row * DM))[threadIdx.x] = ((const float4*)src)[threadIdx.x];
}

// transpose conv_w (NL, o, d, r) -> wc[layer][k=r*512+d][o]
__global__ void convwT_k(const float* __restrict__ cw, float* __restrict__ wc)
{
    const int total = NLAYERS * RRATIO * DM * DM;
    for (int idx = blockIdx.x * blockDim.x + threadIdx.x; idx < total; idx += gridDim.x * blockDim.x) {
        const int layer = idx / (RRATIO * DM * DM);
        const int rem   = idx % (RRATIO * DM * DM);
        const int k = rem / DM, o = rem % DM;
        wc[idx] = cw[(size_t)layer * RRATIO * DM * DM + (size_t)o * (RRATIO * DM) + (k & 511) * 4 + (k >> 9)];
    }
}

__global__ __launch_bounds__(256) void mse_k(const float* __restrict__ a,
                                             const float* __restrict__ b,
                                             float* __restrict__ part)
{
    __shared__ float sh[256];
    float s = 0.f;
    for (int idx = blockIdx.x * 256 + threadIdx.x; idx < MROWS * DM; idx += 128 * 256) {
        const float d = a[idx] - b[idx];
        s += d * d;
    }
    sh[threadIdx.x] = s; __syncthreads();
    for (int o = 128; o > 0; o >>= 1) { if (threadIdx.x < o) sh[threadIdx.x] += sh[threadIdx.x + o]; __syncthreads(); }
    if (threadIdx.x == 0) part[blockIdx.x] = sh[0];
}

__global__ void copyout_k(const float* __restrict__ x, float* __restrict__ out)
{
    const int total = MROWS * (DM / 4);
    for (int idx = blockIdx.x * blockDim.x + threadIdx.x; idx < total; idx += gridDim.x * blockDim.x)
        ((float4*)out)[idx] = ((const float4*)x)[idx];
}

__global__ __launch_bounds__(128) void loss_k(const float* __restrict__ part,
                                              float* __restrict__ out, int out_size)
{
    __shared__ float sh[128];
    float s = 0.f;
    for (int j = threadIdx.x; j < NLAYERS * 128; j += 128) s += part[j];
    sh[threadIdx.x] = s; __syncthreads();
    for (int o = 64; o > 0; o >>= 1) { if (threadIdx.x < o) sh[threadIdx.x] += sh[threadIdx.x + o]; __syncthreads(); }
    if (threadIdx.x == 0 && out_size > MROWS * DM)
        out[MROWS * DM] = sh[0] * (1.0f / ((float)(MROWS * DM) * (float)NLAYERS));
}

// ---------------------------------------------------------------------------
// Host driver
// ---------------------------------------------------------------------------
extern "C" void kernel_launch(void* const* d_in, const int* in_sizes, int n_in,
                              void* d_out, int out_size)
{
    (void)in_sizes; (void)n_in;
    const int*   trg     = (const int*)  d_in[0];
    const float* latent  = (const float*)d_in[3];
    const float* mems    = (const float*)d_in[4];
    const float* cmems   = (const float*)d_in[5];
    const float* pos_emb = (const float*)d_in[6];
    const float* embed   = (const float*)d_in[7];
    const float* W_self  = (const float*)d_in[8];
    const float* ln1_g   = (const float*)d_in[9];
    const float* ln1_b   = (const float*)d_in[10];
    const float* conv_w  = (const float*)d_in[11];
    const float* conv_b  = (const float*)d_in[12];
    const float* W_src   = (const float*)d_in[13];
    const float* ln2_g   = (const float*)d_in[14];
    const float* ln2_b   = (const float*)d_in[15];
    const float* w1      = (const float*)d_in[16];
    const float* b1      = (const float*)d_in[17];
    const float* w2      = (const float*)d_in[18];
    const float* b2      = (const float*)d_in[19];

    float *x,*kv,*q,*k,*v,*dots,*pos,*ao,*t1,*t2,*cm,*kcm,*vcm,*y,*ff,*wc,*sk,*part;
    cudaGetSymbolAddress((void**)&x,   g_x);
    cudaGetSymbolAddress((void**)&kv,  g_kv);
    cudaGetSymbolAddress((void**)&q,   g_q);
    cudaGetSymbolAddress((void**)&k,   g_k);
    cudaGetSymbolAddress((void**)&v,   g_v);
    cudaGetSymbolAddress((void**)&dots,g_dots);
    cudaGetSymbolAddress((void**)&pos, g_pos);
    cudaGetSymbolAddress((void**)&ao,  g_ao);
    cudaGetSymbolAddress((void**)&t1,  g_t1);
    cudaGetSymbolAddress((void**)&t2,  g_t2);
    cudaGetSymbolAddress((void**)&cm,  g_cm);
    cudaGetSymbolAddress((void**)&kcm, g_kcm);
    cudaGetSymbolAddress((void**)&vcm, g_vcm);
    cudaGetSymbolAddress((void**)&y,   g_y);
    cudaGetSymbolAddress((void**)&ff,  g_ff);
    cudaGetSymbolAddress((void**)&wc,  g_wc);
    cudaGetSymbolAddress((void**)&sk,  g_sk);
    cudaGetSymbolAddress((void**)&part,g_part);

    embed_k<<<256, 256>>>(trg, embed, x);
    convwT_k<<<2048, 256>>>(conv_w, wc);

    for (int i = 0; i < NLAYERS; i++) {
        const float* Wq  = W_self + ((size_t)i * 4 + 0) * DM * DM;
        const float* Wk  = W_self + ((size_t)i * 4 + 1) * DM * DM;
        const float* Wv  = W_self + ((size_t)i * 4 + 2) * DM * DM;
        const float* Wo  = W_self + ((size_t)i * 4 + 3) * DM * DM;
        const float* Wq2 = W_src  + ((size_t)i * 4 + 0) * DM * DM;
        const float* Wk2 = W_src  + ((size_t)i * 4 + 1) * DM * DM;
        const float* Wv2 = W_src  + ((size_t)i * 4 + 2) * DM * DM;
        const float* Wo2 = W_src  + ((size_t)i * 4 + 3) * DM * DM;
        const float* mems_i  = mems  + (size_t)i * NB * MEMN * DM;
        const float* cmems_i = cmems + (size_t)i * NB * CMEMN * DM;

        // ---- self attention (batched q/k/v projection) ----
        kvbuild_k<<<NB * KVN, 128>>>(cmems_i, mems_i, x, kv);
        sgemm_k<<<dim3(8, 36, 3), 256>>>(x,  Wq, q, MROWS,
                                         kv, Wk, k, NB * KVN,
                                         kv, Wv, v, NB * KVN,
                                         DM, DM, 0, nullptr, nullptr);
        scores_k<<<dim3(18, 8, 32), 256>>>(q, k,       dots, KVN, DM, (long)KVN * DM, 64,             0.125f, 0);
        scores_k<<<dim3(18, 8, 32), 256>>>(q, pos_emb, pos,  KVN, DH, 0,              (long)KVN * DH, 8.0f,   1);
        softmax_k<<<dim3(SQ, 32), 128>>>(dots, pos, KVN, 1);
        av_k<<<dim3(1, 8, 32), 256>>>(dots, v, ao, KVN);
        sgemm_k<<<dim3(8, 16, 1), 256>>>(ao, Wo, y, MROWS,
                                         nullptr, nullptr, nullptr, 0,
                                         nullptr, nullptr, nullptr, 0,
                                         DM, DM, 1, nullptr, x);
        ln_k<<<MROWS, 128>>>(y, ln1_g + i * DM, ln1_b + i * DM, x);

        // ---- conv compress (GEMM, split-K=4) ----
        sgemm_splitk_k<<<dim3(8, 4, 4), 256>>>(mems_i, wc + (size_t)i * RRATIO * DM * DM,
                                               sk, NB * CMEMN, DM, RRATIO * DM, DM);
        redk_k<<<256, 256>>>(sk, 4, NB * CMEMN * DM, DM, 2, conv_b + i * DM, nullptr, cm);

        // ---- reconstruction attention loss (batched q/k/v) ----
        sgemm_k<<<dim3(8, 16, 3), 256>>>(x,      Wq, q, MROWS,
                                         mems_i, Wk, k, MROWS,
                                         mems_i, Wv, v, MROWS,
                                         DM, DM, 0, nullptr, nullptr);
        scores_k<<<dim3(8, 8, 32), 256>>>(q, k, dots, MEMN, DM, (long)MEMN * DM, 64, 0.125f, 0);
        softmax_k<<<dim3(SQ, 32), 128>>>(dots, pos, MEMN, 0);
        av_k<<<dim3(1, 8, 32), 256>>>(dots, v, t1, MEMN);
        sgemm_k<<<dim3(8, 4, 2), 256>>>(cm, Wk, kcm, NB * CMEMN,
                                        cm, Wv, vcm, NB * CMEMN,
                                        nullptr, nullptr, nullptr, 0,
                                        DM, DM, 0, nullptr, nullptr);
        scores_k<<<dim3(2, 8, 32), 256>>>(q, kcm, dots, CMEMN, DM, (long)CMEMN * DM, 64, 0.125f, 0);
        softmax_k<<<dim3(SQ, 32), 128>>>(dots, pos, CMEMN, 0);
        av_k<<<dim3(1, 8, 32), 256>>>(dots, vcm, t2, CMEMN);
        mse_k<<<128, 256>>>(t1, t2, part + i * 128);

        // ---- cross attention to latent (batched q/k/v) ----
        sgemm_k<<<dim3(8, 16, 3), 256>>>(x,      Wq2, q, MROWS,
                                         latent, Wk2, k, NB * LLAT,
                                         latent, Wv2, v, NB * LLAT,
                                         DM, DM, 0, nullptr, nullptr);
        scores_k<<<dim3(4, 8, 32), 256>>>(q, k, dots, LLAT, DM, (long)LLAT * DM, 64, 0.125f, 0);
        softmax_k<<<dim3(SQ, 32), 128>>>(dots, pos, LLAT, 0);
        av_k<<<dim3(1, 8, 32), 256>>>(dots, v, ao, LLAT);
        sgemm_k<<<dim3(8, 16, 1), 256>>>(ao, Wo2, x, MROWS,
                                         nullptr, nullptr, nullptr, 0,
                                         nullptr, nullptr, nullptr, 0,
                                         DM, DM, 0, nullptr, nullptr);

        // ---- feed-forward ----
        ln_k<<<MROWS, 128>>>(x, ln2_g + i * DM, ln2_b + i * DM, y);
        sgemm_k<<<dim3(32, 16, 1), 256>>>(y, w1 + (size_t)i * DM * FFD, ff, MROWS,
                                          nullptr, nullptr, nullptr, 0,
                                          nullptr, nullptr, nullptr, 0,
                                          FFD, DM, 3, b1 + (size_t)i * FFD, nullptr);
        sgemm_splitk_k<<<dim3(8, 16, 2), 256>>>(ff, w2 + (size_t)i * FFD * DM,
                                                sk, MROWS, DM, FFD, FFD / 2);
        redk_k<<<512, 256>>>(sk, 2, MROWS * DM, DM, 4, b2 + i * DM, x, x);
    }

    copyout_k<<<512, 256>>>(x, (float*)d_out);
    loss_k<<<1, 128>>>(part, (float*)d_out, out_size);
}

// round 12
// speedup vs baseline: 1.2004x; 1.1812x over previous
#include <cuda_runtime.h>
#include <math.h>
#include <stdint.h>

// ---------------------------------------------------------------------------
// Problem constants
// ---------------------------------------------------------------------------
#define NLAYERS 4
#define NB      4
#define SQ      512
#define DM      512
#define NH      8
#define DH      64
#define MEMN    512
#define CMEMN   128
#define RRATIO  4
#define LLAT    256
#define FFD     2048
#define KVN     (CMEMN + MEMN + SQ)   // 1152
#define MROWS   (NB * SQ)             // 2048

// ---------------------------------------------------------------------------
// Scratch (device globals)
// ---------------------------------------------------------------------------
__device__ float g_x  [MROWS * DM];
__device__ float g_kv [NB * KVN * DM];
__device__ float g_q  [MROWS * DM];
__device__ float g_k  [NB * KVN * DM];
__device__ float g_v  [NB * KVN * DM];
__device__ float g_dots[(size_t)NB * NH * SQ * KVN];
__device__ float g_pos [(size_t)NB * NH * SQ * KVN];
__device__ float g_ao [MROWS * DM];
__device__ float g_t1 [MROWS * DM];
__device__ float g_t2 [MROWS * DM];
__device__ float g_cm [NB * CMEMN * DM];
__device__ float g_kcm[NB * CMEMN * DM];
__device__ float g_vcm[NB * CMEMN * DM];
__device__ float g_y  [MROWS * DM];
__device__ float g_ff [MROWS * FFD];
__device__ float g_wc [NLAYERS * RRATIO * DM * DM];
__device__ float g_sk [4 * 1024 * 1024];          // split-K partials
__device__ float g_part[NLAYERS * 128];

// ---------------------------------------------------------------------------
// Packed fp32x2 helpers (Blackwell FFMA2)
// ---------------------------------------------------------------------------
__device__ __forceinline__ unsigned long long pk2(float lo, float hi) {
    unsigned long long r;
    asm("mov.b64 %0, {%1,%2};" : "=l"(r) : "f"(lo), "f"(hi));
    return r;
}
__device__ __forceinline__ void upk2(unsigned long long v, float& lo, float& hi) {
    asm("mov.b64 {%0,%1}, %2;" : "=f"(lo), "=f"(hi) : "l"(v));
}
__device__ __forceinline__ void fma2(unsigned long long& d, unsigned long long a,
                                     unsigned long long b) {
    asm("fma.rn.f32x2 %0, %1, %2, %0;" : "+l"(d) : "l"(a), "l"(b));
}

// ---------------------------------------------------------------------------
// GEMM core: C[M,N] = A[M,K(full stride)] @ B[K,N] over k in [kBeg,kEnd)
// BM=128, BN=64, BK=16, 256 threads, 8x4 outputs/thread via 4x4 f32x2 accs.
// A smem [k][m]: read directly as u64 m-pairs (zero packing MOVs, same bytes).
// B smem compact float4 (R5 layout — pre-duplication proven harmful).
// epi: 0 none, 1 +resid, 2 +bias, 3 gelu(.+bias), 4 +bias+resid
// ---------------------------------------------------------------------------
__device__ __forceinline__ void gemm_body(
    const float* __restrict__ A, const float* __restrict__ Bw, float* __restrict__ C,
    int N, int K, int kBeg, int kEnd,
    int epi, const float* __restrict__ bias, const float* __restrict__ resid)
{
    __shared__ __align__(16) float As[2][16][132];
    __shared__ __align__(16) float Bs[2][16][64];
    const int tid  = threadIdx.x;
    const int tx   = tid & 15, ty = tid >> 4;
    const int row0 = blockIdx.y * 128, col0 = blockIdx.x * 64;
    const int ar   = tid >> 2,  ak = (tid & 3) << 2;
    const int br   = tid >> 4,  bc = (tid & 15) << 2;
    const float* Ag = A + (size_t)row0 * K + kBeg;
    const float* Bg = Bw + (size_t)kBeg * N + col0;

    unsigned long long acc[4][4];
#pragma unroll
    for (int m = 0; m < 4; m++)
#pragma unroll
        for (int n = 0; n < 4; n++) acc[m][n] = 0ull;

    const int nk = (kEnd - kBeg) >> 4;
    float4 a0 = *(const float4*)(Ag + (size_t)ar        * K + ak);
    float4 a1 = *(const float4*)(Ag + (size_t)(ar + 64) * K + ak);
    float4 b0 = *(const float4*)(Bg + (size_t)br * N + bc);
    As[0][ak+0][ar]    = a0.x; As[0][ak+1][ar]    = a0.y; As[0][ak+2][ar]    = a0.z; As[0][ak+3][ar]    = a0.w;
    As[0][ak+0][ar+64] = a1.x; As[0][ak+1][ar+64] = a1.y; As[0][ak+2][ar+64] = a1.z; As[0][ak+3][ar+64] = a1.w;
    *(float4*)&Bs[0][br][bc] = b0;
    __syncthreads();

    int buf = 0;
    for (int t = 0; t < nk; t++) {
        const bool more = (t + 1 < nk);
        if (more) {
            const float* Ag2 = Ag + (t + 1) * 16;
            a0 = *(const float4*)(Ag2 + (size_t)ar        * K + ak);
            a1 = *(const float4*)(Ag2 + (size_t)(ar + 64) * K + ak);
            b0 = *(const float4*)(Bg + (size_t)((t + 1) * 16 + br) * N + bc);
        }
#pragma unroll
        for (int k = 0; k < 16; k++) {
            // A as direct u64 pairs (pairs run along M, matching accumulator pairs)
            const unsigned long long* Ap =
                (const unsigned long long*)(&As[buf][k][ty * 8]);
            unsigned long long am0 = Ap[0];
            unsigned long long am1 = Ap[1];
            unsigned long long am2 = Ap[2];
            unsigned long long am3 = Ap[3];
            float4 bv = *(const float4*)&Bs[buf][k][tx*4];
            unsigned long long bd[4] = { pk2(bv.x, bv.x), pk2(bv.y, bv.y),
                                         pk2(bv.z, bv.z), pk2(bv.w, bv.w) };
#pragma unroll
            for (int n = 0; n < 4; n++) {
                fma2(acc[0][n], am0, bd[n]);
                fma2(acc[1][n], am1, bd[n]);
                fma2(acc[2][n], am2, bd[n]);
                fma2(acc[3][n], am3, bd[n]);
            }
        }
        if (more) {
            const int nb = buf ^ 1;
            As[nb][ak+0][ar]    = a0.x; As[nb][ak+1][ar]    = a0.y; As[nb][ak+2][ar]    = a0.z; As[nb][ak+3][ar]    = a0.w;
            As[nb][ak+0][ar+64] = a1.x; As[nb][ak+1][ar+64] = a1.y; As[nb][ak+2][ar+64] = a1.z; As[nb][ak+3][ar+64] = a1.w;
            *(float4*)&Bs[nb][br][bc] = b0;
        }
        __syncthreads();
        buf ^= 1;
    }

    const int c0 = col0 + tx * 4;
#pragma unroll
    for (int m2 = 0; m2 < 4; m2++) {
        const int r = row0 + ty * 8 + m2 * 2;
        float lo[4], hi[4];
#pragma unroll
        for (int n = 0; n < 4; n++) upk2(acc[m2][n], lo[n], hi[n]);
        if (epi == 2 || epi == 3 || epi == 4) {
            float4 bb = *(const float4*)(bias + c0);
            lo[0]+=bb.x; lo[1]+=bb.y; lo[2]+=bb.z; lo[3]+=bb.w;
            hi[0]+=bb.x; hi[1]+=bb.y; hi[2]+=bb.z; hi[3]+=bb.w;
        }
        if (epi == 3) {
#pragma unroll
            for (int n = 0; n < 4; n++) {
                lo[n] = 0.5f * lo[n] * (1.0f + erff(lo[n] * 0.70710678118654752440f));
                hi[n] = 0.5f * hi[n] * (1.0f + erff(hi[n] * 0.70710678118654752440f));
            }
        }
        if (epi == 1 || epi == 4) {
            float4 r0 = *(const float4*)(resid + (size_t)r * N + c0);
            float4 r1 = *(const float4*)(resid + (size_t)(r + 1) * N + c0);
            lo[0]+=r0.x; lo[1]+=r0.y; lo[2]+=r0.z; lo[3]+=r0.w;
            hi[0]+=r1.x; hi[1]+=r1.y; hi[2]+=r1.z; hi[3]+=r1.w;
        }
        *(float4*)(C + (size_t)r       * N + c0) = make_float4(lo[0], lo[1], lo[2], lo[3]);
        *(float4*)(C + (size_t)(r + 1) * N + c0) = make_float4(hi[0], hi[1], hi[2], hi[3]);
    }
}

// z-batched SGEMM (up to 3 problems sharing N, K; early-exit past M_z)
__global__ __launch_bounds__(256, 2) void sgemm_k(
    const float* A0, const float* B0, float* C0, int M0,
    const float* A1, const float* B1, float* C1, int M1,
    const float* A2, const float* B2, float* C2, int M2,
    int N, int K, int epi, const float* bias, const float* resid)
{
    const int z = blockIdx.z;
    const float* A  = (z == 0) ? A0 : (z == 1) ? A1 : A2;
    const float* Bw = (z == 0) ? B0 : (z == 1) ? B1 : B2;
    float*       C  = (z == 0) ? C0 : (z == 1) ? C1 : C2;
    const int    M  = (z == 0) ? M0 : (z == 1) ? M1 : M2;
    if (blockIdx.y * 128 >= M) return;
    gemm_body(A, Bw, C, N, K, 0, K, epi, bias, resid);
}

// split-K SGEMM: z = K-chunk, writes partials Cpart[z][M][N]
__global__ __launch_bounds__(256, 2) void sgemm_splitk_k(
    const float* A, const float* Bw, float* Cpart, int M, int N, int K, int KC)
{
    const int z = blockIdx.z;
    gemm_body(A, Bw, Cpart + (size_t)z * M * N, N, K, z * KC, z * KC + KC,
              0, nullptr, nullptr);
}

// split-K reduce + epilogue (deterministic order)
__global__ void redk_k(const float* __restrict__ parts, int nparts, int total, int N,
                       int epi, const float* __restrict__ bias,
                       const float* __restrict__ resid, float* __restrict__ out)
{
    for (int idx = blockIdx.x * blockDim.x + threadIdx.x; idx < total;
         idx += gridDim.x * blockDim.x) {
        float s = parts[idx];
        for (int p = 1; p < nparts; p++) s += parts[(size_t)p * total + idx];
        const int c = idx % N;
        if (epi == 2) s += bias[c];
        else if (epi == 4) s += bias[c] + resid[idx];
        out[idx] = s;
    }
}

// ---------------------------------------------------------------------------
// Attention scores: out[bh,i,j] = scale * sum_d Q[b,i,h,d] * Kb[...,j,d]
// shiftSkip=1: skip blocks never read through the shift() gather (pos scores)
// ---------------------------------------------------------------------------
__global__ __launch_bounds__(256, 3) void scores_k(
    const float* __restrict__ Q, const float* __restrict__ Kb,
    float* __restrict__ out, int L, int ldb, long bSB, long bSH, float scale,
    int shiftSkip)
{
    const int i0 = blockIdx.y * 64, j0 = blockIdx.x * 64;
    if (shiftSkip && (i0 + j0 <= 384)) return;   // fully-dead pos blocks
    __shared__ __align__(16) float Qs[64][68];  // [d][i]
    __shared__ __align__(16) float Ks[64][68];  // [d][j]
    const int bh = blockIdx.z, b = bh >> 3, h = bh & 7;
    const float* Qg = Q + ((size_t)(b * SQ + i0)) * DM + h * DH;
    const float* Kg = Kb + (size_t)b * bSB + (size_t)h * bSH + (size_t)j0 * ldb;
    const int tid = threadIdx.x;
    const int rr = tid >> 4, c4 = (tid & 15) << 2;
#pragma unroll
    for (int s = 0; s < 4; s++) {
        const int r = rr + s * 16;
        float4 qv = *(const float4*)(Qg + (size_t)r * DM + c4);
        Qs[c4+0][r] = qv.x; Qs[c4+1][r] = qv.y; Qs[c4+2][r] = qv.z; Qs[c4+3][r] = qv.w;
        float4 kv2 = *(const float4*)(Kg + (size_t)r * ldb + c4);
        Ks[c4+0][r] = kv2.x; Ks[c4+1][r] = kv2.y; Ks[c4+2][r] = kv2.z; Ks[c4+3][r] = kv2.w;
    }
    __syncthreads();
    const int tx = tid & 15, ty = tid >> 4;
    unsigned long long acc[2][4];
#pragma unroll
    for (int m = 0; m < 2; m++)
#pragma unroll
        for (int n = 0; n < 4; n++) acc[m][n] = 0ull;
#pragma unroll
    for (int d = 0; d < 64; d++) {
        const unsigned long long* Ap = (const unsigned long long*)(&Qs[d][ty*4]);
        unsigned long long am0 = Ap[0];
        unsigned long long am1 = Ap[1];
        float4 bv = *(const float4*)&Ks[d][tx*4];
        unsigned long long bd[4] = { pk2(bv.x, bv.x), pk2(bv.y, bv.y),
                                     pk2(bv.z, bv.z), pk2(bv.w, bv.w) };
#pragma unroll
        for (int n = 0; n < 4; n++) {
            fma2(acc[0][n], am0, bd[n]);
            fma2(acc[1][n], am1, bd[n]);
        }
    }
    float* Og = out + ((long)bh * SQ + i0) * (long)L + j0 + tx * 4;
#pragma unroll
    for (int m2 = 0; m2 < 2; m2++) {
        float lo[4], hi[4];
#pragma unroll
        for (int n = 0; n < 4; n++) upk2(acc[m2][n], lo[n], hi[n]);
        *(float4*)(Og + (long)(ty*4 + 2*m2)     * L) =
            make_float4(lo[0]*scale, lo[1]*scale, lo[2]*scale, lo[3]*scale);
        *(float4*)(Og + (long)(ty*4 + 2*m2 + 1) * L) =
            make_float4(hi[0]*scale, hi[1]*scale, hi[2]*scale, hi[3]*scale);
    }
}

// ---------------------------------------------------------------------------
// AV: out[b,i,h,d] = sum_j P[bh,i,j] * V[b,j,h,d]
// ---------------------------------------------------------------------------
__global__ __launch_bounds__(256, 3) void av_k(
    const float* __restrict__ P, const float* __restrict__ V,
    float* __restrict__ out, int L)
{
    __shared__ __align__(16) float Ps[64][68];  // [j][i]
    __shared__ __align__(16) float Vs[64][68];  // [j][d]
    const int bh = blockIdx.z, b = bh >> 3, h = bh & 7;
    const int i0 = blockIdx.y * 64;
    const float* Pg = P + ((long)bh * SQ + i0) * (long)L;
    const float* Vg = V + (size_t)b * L * DM + h * DH;
    const int tid = threadIdx.x;
    const int rr = tid >> 4, c4 = (tid & 15) << 2;
    const int tx = tid & 15, ty = tid >> 4;
    unsigned long long acc[2][4];
#pragma unroll
    for (int m = 0; m < 2; m++)
#pragma unroll
        for (int n = 0; n < 4; n++) acc[m][n] = 0ull;
    for (int j0 = 0; j0 < L; j0 += 64) {
#pragma unroll
        for (int s = 0; s < 4; s++) {
            const int r = rr + s * 16;
            float4 pv = *(const float4*)(Pg + (long)r * L + j0 + c4);
            Ps[c4+0][r] = pv.x; Ps[c4+1][r] = pv.y; Ps[c4+2][r] = pv.z; Ps[c4+3][r] = pv.w;
            float4 vv = *(const float4*)(Vg + (size_t)(j0 + r) * DM + c4);
            *(float4*)&Vs[r][c4] = vv;
        }
        __syncthreads();
#pragma unroll
        for (int j = 0; j < 64; j++) {
            const unsigned long long* Ap = (const unsigned long long*)(&Ps[j][ty*4]);
            unsigned long long am0 = Ap[0];
            unsigned long long am1 = Ap[1];
            float4 bv = *(const float4*)&Vs[j][tx*4];
            unsigned long long bd[4] = { pk2(bv.x, bv.x), pk2(bv.y, bv.y),
                                         pk2(bv.z, bv.z), pk2(bv.w, bv.w) };
#pragma unroll
            for (int n = 0; n < 4; n++) {
                fma2(acc[0][n], am0, bd[n]);
                fma2(acc[1][n], am1, bd[n]);
            }
        }
        __syncthreads();
    }
    float* Og = out + ((size_t)(b * SQ + i0)) * DM + h * DH + tx * 4;
#pragma unroll
    for (int m2 = 0; m2 < 2; m2++) {
        float lo[4], hi[4];
#pragma unroll
        for (int n = 0; n < 4; n++) upk2(acc[m2][n], lo[n], hi[n]);
        *(float4*)(Og + (size_t)(ty*4 + 2*m2)     * DM) = make_float4(lo[0], lo[1], lo[2], lo[3]);
        *(float4*)(Og + (size_t)(ty*4 + 2*m2 + 1) * DM) = make_float4(hi[0], hi[1], hi[2], hi[3]);
    }
}

// ---------------------------------------------------------------------------
// Softmax over row of length L (multiple of 128), optional shifted pos add
// ---------------------------------------------------------------------------
__global__ __launch_bounds__(128) void softmax_k(
    float* __restrict__ dots, const float* __restrict__ posR, int L, int usePos)
{
    const int i = blockIdx.x, bh = blockIdx.y;
    float* row = dots + ((long)bh * SQ + i) * (long)L;
    const float* prow = posR + ((long)bh * SQ + i) * (long)KVN;
    const int tid = threadIdx.x;
    const int nper = L >> 7;
    float vals[9];
    float mx = -1e30f;
    for (int t = 0; t < nper; t++) {
        const int j = tid + t * 128;
        float vv = row[j];
        if (usePos) {
            const int jp = j + (SQ - 1) - i;
            if (jp < KVN) vv += prow[jp];
        }
        vals[t] = vv;
        mx = fmaxf(mx, vv);
    }
    __shared__ float sh[128];
    sh[tid] = mx; __syncthreads();
    for (int o = 64; o > 0; o >>= 1) { if (tid < o) sh[tid] = fmaxf(sh[tid], sh[tid + o]); __syncthreads(); }
    mx = sh[0]; __syncthreads();
    float s = 0.f;
    for (int t = 0; t < nper; t++) { vals[t] = __expf(vals[t] - mx); s += vals[t]; }
    sh[tid] = s; __syncthreads();
    for (int o = 64; o > 0; o >>= 1) { if (tid < o) sh[tid] += sh[tid + o]; __syncthreads(); }
    const float inv = 1.0f / sh[0];
    for (int t = 0; t < nper; t++) row[tid + t * 128] = vals[t] * inv;
}

// ---------------------------------------------------------------------------
// LayerNorm over D=512
// ---------------------------------------------------------------------------
__global__ __launch_bounds__(128) void ln_k(
    const float* __restrict__ x, const float* __restrict__ g,
    const float* __restrict__ bt, float* __restrict__ out)
{
    const int row = blockIdx.x, tid = threadIdx.x;
    const float* xr = x + (size_t)row * DM;
    float v[4]; float s = 0.f, s2 = 0.f;
#pragma unroll
    for (int t = 0; t < 4; t++) { v[t] = xr[tid + t * 128]; s += v[t]; s2 += v[t] * v[t]; }
    __shared__ float sa[128], sb[128];
    sa[tid] = s; sb[tid] = s2; __syncthreads();
    for (int o = 64; o > 0; o >>= 1) { if (tid < o) { sa[tid] += sa[tid+o]; sb[tid] += sb[tid+o]; } __syncthreads(); }
    const float mean = sa[0] * (1.0f / DM);
    const float var  = sb[0] * (1.0f / DM) - mean * mean;
    const float rs   = rsqrtf(var + 1e-5f);
    float* orow = out + (size_t)row * DM;
#pragma unroll
    for (int t = 0; t < 4; t++) {
        const int c = tid + t * 128;
        orow[c] = (v[t] - mean) * rs * g[c] + bt[c];
    }
}

// ---------------------------------------------------------------------------
// Misc kernels
// ---------------------------------------------------------------------------
__global__ void embed_k(const int* __restrict__ trg, const float* __restrict__ emb,
                        float* __restrict__ x)
{
    const int total = MROWS * (DM / 4);
    for (int idx = blockIdx.x * blockDim.x + threadIdx.x; idx < total; idx += gridDim.x * blockDim.x) {
        const int row = idx >> 7, c = idx & 127;
        ((float4*)x)[idx] = ((const float4*)emb)[(size_t)trg[row] * 128 + c];
    }
}

__global__ void kvbuild_k(const float* __restrict__ cm, const float* __restrict__ mem,
                          const float* __restrict__ x, float* __restrict__ kv)
{
    const int row = blockIdx.x;
    const int b = row / KVN, p = row % KVN;
    const float* src;
    if (p < CMEMN)             src = cm  + ((size_t)b * CMEMN + p) * DM;
    else if (p < CMEMN + MEMN) src = mem + ((size_t)b * MEMN + (p - CMEMN)) * DM;
    else                       src = x   + ((size_t)b * SQ + (p - CMEMN - MEMN)) * DM;
    ((float4*)(kv + (size_t)row * DM))[threadIdx.x] = ((const float4*)src)[threadIdx.x];
}

// transpose conv_w (NL, o, d, r) -> wc[layer][k=r*512+d][o]
__global__ void convwT_k(const float* __restrict__ cw, float* __restrict__ wc)
{
    const int total = NLAYERS * RRATIO * DM * DM;
    for (int idx = blockIdx.x * blockDim.x + threadIdx.x; idx < total; idx += gridDim.x * blockDim.x) {
        const int layer = idx / (RRATIO * DM * DM);
        const int rem   = idx % (RRATIO * DM * DM);
        const int k = rem / DM, o = rem % DM;
        wc[idx] = cw[(size_t)layer * RRATIO * DM * DM + (size_t)o * (RRATIO * DM) + (k & 511) * 4 + (k >> 9)];
    }
}

__global__ __launch_bounds__(256) void mse_k(const float* __restrict__ a,
                                             const float* __restrict__ b,
                                             float* __restrict__ part)
{
    __shared__ float sh[256];
    float s = 0.f;
    for (int idx = blockIdx.x * 256 + threadIdx.x; idx < MROWS * DM; idx += 128 * 256) {
        const float d = a[idx] - b[idx];
        s += d * d;
    }
    sh[threadIdx.x] = s; __syncthreads();
    for (int o = 128; o > 0; o >>= 1) { if (threadIdx.x < o) sh[threadIdx.x] += sh[threadIdx.x + o]; __syncthreads(); }
    if (threadIdx.x == 0) part[blockIdx.x] = sh[0];
}

__global__ void copyout_k(const float* __restrict__ x, float* __restrict__ out)
{
    const int total = MROWS * (DM / 4);
    for (int idx = blockIdx.x * blockDim.x + threadIdx.x; idx < total; idx += gridDim.x * blockDim.x)
        ((float4*)out)[idx] = ((const float4*)x)[idx];
}

__global__ __launch_bounds__(128) void loss_k(const float* __restrict__ part,
                                              float* __restrict__ out, int out_size)
{
    __shared__ float sh[128];
    float s = 0.f;
    for (int j = threadIdx.x; j < NLAYERS * 128; j += 128) s += part[j];
    sh[threadIdx.x] = s; __syncthreads();
    for (int o = 64; o > 0; o >>= 1) { if (threadIdx.x < o) sh[threadIdx.x] += sh[threadIdx.x + o]; __syncthreads(); }
    if (threadIdx.x == 0 && out_size > MROWS * DM)
        out[MROWS * DM] = sh[0] * (1.0f / ((float)(MROWS * DM) * (float)NLAYERS));
}

// ---------------------------------------------------------------------------
// Host driver
// ---------------------------------------------------------------------------
extern "C" void kernel_launch(void* const* d_in, const int* in_sizes, int n_in,
                              void* d_out, int out_size)
{
    (void)in_sizes; (void)n_in;
    const int*   trg     = (const int*)  d_in[0];
    const float* latent  = (const float*)d_in[3];
    const float* mems    = (const float*)d_in[4];
    const float* cmems   = (const float*)d_in[5];
    const float* pos_emb = (const float*)d_in[6];
    const float* embed   = (const float*)d_in[7];
    const float* W_self  = (const float*)d_in[8];
    const float* ln1_g   = (const float*)d_in[9];
    const float* ln1_b   = (const float*)d_in[10];
    const float* conv_w  = (const float*)d_in[11];
    const float* conv_b  = (const float*)d_in[12];
    const float* W_src   = (const float*)d_in[13];
    const float* ln2_g   = (const float*)d_in[14];
    const float* ln2_b   = (const float*)d_in[15];
    const float* w1      = (const float*)d_in[16];
    const float* b1      = (const float*)d_in[17];
    const float* w2      = (const float*)d_in[18];
    const float* b2      = (const float*)d_in[19];

    float *x,*kv,*q,*k,*v,*dots,*pos,*ao,*t1,*t2,*cm,*kcm,*vcm,*y,*ff,*wc,*sk,*part;
    cudaGetSymbolAddress((void**)&x,   g_x);
    cudaGetSymbolAddress((void**)&kv,  g_kv);
    cudaGetSymbolAddress((void**)&q,   g_q);
    cudaGetSymbolAddress((void**)&k,   g_k);
    cudaGetSymbolAddress((void**)&v,   g_v);
    cudaGetSymbolAddress((void**)&dots,g_dots);
    cudaGetSymbolAddress((void**)&pos, g_pos);
    cudaGetSymbolAddress((void**)&ao,  g_ao);
    cudaGetSymbolAddress((void**)&t1,  g_t1);
    cudaGetSymbolAddress((void**)&t2,  g_t2);
    cudaGetSymbolAddress((void**)&cm,  g_cm);
    cudaGetSymbolAddress((void**)&kcm, g_kcm);
    cudaGetSymbolAddress((void**)&vcm, g_vcm);
    cudaGetSymbolAddress((void**)&y,   g_y);
    cudaGetSymbolAddress((void**)&ff,  g_ff);
    cudaGetSymbolAddress((void**)&wc,  g_wc);
    cudaGetSymbolAddress((void**)&sk,  g_sk);
    cudaGetSymbolAddress((void**)&part,g_part);

    embed_k<<<256, 256>>>(trg, embed, x);
    convwT_k<<<2048, 256>>>(conv_w, wc);

    for (int i = 0; i < NLAYERS; i++) {
        const float* Wq  = W_self + ((size_t)i * 4 + 0) * DM * DM;
        const float* Wk  = W_self + ((size_t)i * 4 + 1) * DM * DM;
        const float* Wv  = W_self + ((size_t)i * 4 + 2) * DM * DM;
        const float* Wo  = W_self + ((size_t)i * 4 + 3) * DM * DM;
        const float* Wq2 = W_src  + ((size_t)i * 4 + 0) * DM * DM;
        const float* Wk2 = W_src  + ((size_t)i * 4 + 1) * DM * DM;
        const float* Wv2 = W_src  + ((size_t)i * 4 + 2) * DM * DM;
        const float* Wo2 = W_src  + ((size_t)i * 4 + 3) * DM * DM;
        const float* mems_i  = mems  + (size_t)i * NB * MEMN * DM;
        const float* cmems_i = cmems + (size_t)i * NB * CMEMN * DM;

        // ---- self attention (batched q/k/v projection) ----
        kvbuild_k<<<NB * KVN, 128>>>(cmems_i, mems_i, x, kv);
        sgemm_k<<<dim3(8, 36, 3), 256>>>(x,  Wq, q, MROWS,
                                         kv, Wk, k, NB * KVN,
                                         kv, Wv, v, NB * KVN,
                                         DM, DM, 0, nullptr, nullptr);
        scores_k<<<dim3(18, 8, 32), 256>>>(q, k,       dots, KVN, DM, (long)KVN * DM, 64,             0.125f, 0);
        scores_k<<<dim3(18, 8, 32), 256>>>(q, pos_emb, pos,  KVN, DH, 0,              (long)KVN * DH, 8.0f,   1);
        softmax_k<<<dim3(SQ, 32), 128>>>(dots, pos, KVN, 1);
        av_k<<<dim3(1, 8, 32), 256>>>(dots, v, ao, KVN);
        sgemm_k<<<dim3(8, 16, 1), 256>>>(ao, Wo, y, MROWS,
                                         nullptr, nullptr, nullptr, 0,
                                         nullptr, nullptr, nullptr, 0,
                                         DM, DM, 1, nullptr, x);
        ln_k<<<MROWS, 128>>>(y, ln1_g + i * DM, ln1_b + i * DM, x);

        // ---- conv compress (GEMM, split-K=4) ----
        sgemm_splitk_k<<<dim3(8, 4, 4), 256>>>(mems_i, wc + (size_t)i * RRATIO * DM * DM,
                                               sk, NB * CMEMN, DM, RRATIO * DM, DM);
        redk_k<<<256, 256>>>(sk, 4, NB * CMEMN * DM, DM, 2, conv_b + i * DM, nullptr, cm);

        // ---- reconstruction attention loss (batched q/k/v) ----
        sgemm_k<<<dim3(8, 16, 3), 256>>>(x,      Wq, q, MROWS,
                                         mems_i, Wk, k, MROWS,
                                         mems_i, Wv, v, MROWS,
                                         DM, DM, 0, nullptr, nullptr);
        scores_k<<<dim3(8, 8, 32), 256>>>(q, k, dots, MEMN, DM, (long)MEMN * DM, 64, 0.125f, 0);
        softmax_k<<<dim3(SQ, 32), 128>>>(dots, pos, MEMN, 0);
        av_k<<<dim3(1, 8, 32), 256>>>(dots, v, t1, MEMN);
        sgemm_k<<<dim3(8, 4, 2), 256>>>(cm, Wk, kcm, NB * CMEMN,
                                        cm, Wv, vcm, NB * CMEMN,
                                        nullptr, nullptr, nullptr, 0,
                                        DM, DM, 0, nullptr, nullptr);
        scores_k<<<dim3(2, 8, 32), 256>>>(q, kcm, dots, CMEMN, DM, (long)CMEMN * DM, 64, 0.125f, 0);
        softmax_k<<<dim3(SQ, 32), 128>>>(dots, pos, CMEMN, 0);
        av_k<<<dim3(1, 8, 32), 256>>>(dots, vcm, t2, CMEMN);
        mse_k<<<128, 256>>>(t1, t2, part + i * 128);

        // ---- cross attention to latent (batched q/k/v) ----
        sgemm_k<<<dim3(8, 16, 3), 256>>>(x,      Wq2, q, MROWS,
                                         latent, Wk2, k, NB * LLAT,
                                         latent, Wv2, v, NB * LLAT,
                                         DM, DM, 0, nullptr, nullptr);
        scores_k<<<dim3(4, 8, 32), 256>>>(q, k, dots, LLAT, DM, (long)LLAT * DM, 64, 0.125f, 0);
        softmax_k<<<dim3(SQ, 32), 128>>>(dots, pos, LLAT, 0);
        av_k<<<dim3(1, 8, 32), 256>>>(dots, v, ao, LLAT);
        sgemm_k<<<dim3(8, 16, 1), 256>>>(ao, Wo2, x, MROWS,
                                         nullptr, nullptr, nullptr, 0,
                                         nullptr, nullptr, nullptr, 0,
                                         DM, DM, 0, nullptr, nullptr);

        // ---- feed-forward ----
        ln_k<<<MROWS, 128>>>(x, ln2_g + i * DM, ln2_b + i * DM, y);
        sgemm_k<<<dim3(32, 16, 1), 256>>>(y, w1 + (size_t)i * DM * FFD, ff, MROWS,
                                          nullptr, nullptr, nullptr, 0,
                                          nullptr, nullptr, nullptr, 0,
                                          FFD, DM, 3, b1 + (size_t)i * FFD, nullptr);
        sgemm_splitk_k<<<dim3(8, 16, 2), 256>>>(ff, w2 + (size_t)i * FFD * DM,
                                                sk, MROWS, DM, FFD, FFD / 2);
        redk_k<<<512, 256>>>(sk, 2, MROWS * DM, DM, 4, b2 + i * DM, x, x);
    }

    copyout_k<<<512, 256>>>(x, (float*)d_out);
    loss_k<<<1, 128>>>(part, (float*)d_out, out_size);
}

// round 14
// speedup vs baseline: 1.4181x; 1.1814x over previous
#include <cuda_runtime.h>
#include <cuda_bf16.h>
#include <math.h>
#include <stdint.h>

// ---------------------------------------------------------------------------
// Problem constants
// ---------------------------------------------------------------------------
#define NLAYERS 4
#define NB      4
#define SQ      512
#define DM      512
#define NH      8
#define DH      64
#define MEMN    512
#define CMEMN   128
#define RRATIO  4
#define LLAT    256
#define FFD     2048
#define KVN     (CMEMN + MEMN + SQ)   // 1152
#define MROWS   (NB * SQ)             // 2048

typedef __nv_bfloat16 bf16;

// ---------------------------------------------------------------------------
// fp32 scratch (device globals)
// ---------------------------------------------------------------------------
__device__ float g_x  [MROWS * DM];
__device__ float g_kv [NB * KVN * DM];
__device__ float g_q  [MROWS * DM];
__device__ float g_k  [NB * KVN * DM];
__device__ float g_v  [NB * KVN * DM];
__device__ float g_dots[(size_t)NB * NH * SQ * KVN];
__device__ float g_pos [(size_t)NB * NH * SQ * KVN];
__device__ float g_ao [MROWS * DM];
__device__ float g_t1 [MROWS * DM];
__device__ float g_t2 [MROWS * DM];
__device__ float g_cm [NB * CMEMN * DM];
__device__ float g_kcm[NB * CMEMN * DM];
__device__ float g_vcm[NB * CMEMN * DM];
__device__ float g_y  [MROWS * DM];
__device__ float g_ff [MROWS * FFD];
__device__ float g_sk [4 * 1024 * 1024];
__device__ float g_part[NLAYERS * 128];

// ---------------------------------------------------------------------------
// bf16 hi/lo planes (activations + weights)
// ---------------------------------------------------------------------------
__device__ bf16 g_xh [MROWS * DM],      g_xl [MROWS * DM];
__device__ bf16 g_kvh[NB * KVN * DM],   g_kvl[NB * KVN * DM];
__device__ bf16 g_aoh[MROWS * DM],      g_aol[MROWS * DM];
__device__ bf16 g_yh [MROWS * DM],      g_yl [MROWS * DM];
__device__ bf16 g_ffh[MROWS * FFD],     g_ffl[MROWS * FFD];
__device__ bf16 g_cmh[NB * CMEMN * DM], g_cml[NB * CMEMN * DM];
__device__ bf16 g_msh[NLAYERS * NB * MEMN * DM], g_msl[NLAYERS * NB * MEMN * DM];
__device__ bf16 g_lth[NB * LLAT * DM],  g_ltl[NB * LLAT * DM];
__device__ bf16 g_Wsh[NLAYERS * 4 * DM * DM], g_Wsl[NLAYERS * 4 * DM * DM];
__device__ bf16 g_Wrh[NLAYERS * 4 * DM * DM], g_Wrl[NLAYERS * 4 * DM * DM];
__device__ bf16 g_w1h[NLAYERS * DM * FFD],    g_w1l[NLAYERS * DM * FFD];
__device__ bf16 g_w2h[NLAYERS * FFD * DM],    g_w2l[NLAYERS * FFD * DM];
__device__ bf16 g_wch[NLAYERS * DM * FFD],    g_wcl[NLAYERS * DM * FFD];

// ---------------------------------------------------------------------------
// Packed fp32x2 helpers (scores/av keep the scalar FFMA2 path)
// ---------------------------------------------------------------------------
__device__ __forceinline__ unsigned long long pk2(float lo, float hi) {
    unsigned long long r;
    asm("mov.b64 %0, {%1,%2};" : "=l"(r) : "f"(lo), "f"(hi));
    return r;
}
__device__ __forceinline__ void upk2(unsigned long long v, float& lo, float& hi) {
    asm("mov.b64 {%0,%1}, %2;" : "=f"(lo), "=f"(hi) : "l"(v));
}
__device__ __forceinline__ void fma2(unsigned long long& d, unsigned long long a,
                                     unsigned long long b) {
    asm("fma.rn.f32x2 %0, %1, %2, %0;" : "+l"(d) : "l"(a), "l"(b));
}

// ---------------------------------------------------------------------------
// MMA helpers
// ---------------------------------------------------------------------------
__device__ __forceinline__ void mma16816(float* c, const uint32_t* a, const uint32_t* b) {
    asm volatile(
        "mma.sync.aligned.m16n8k16.row.col.f32.bf16.bf16.f32 "
        "{%0,%1,%2,%3},{%4,%5,%6,%7},{%8,%9},{%0,%1,%2,%3};"
        : "+f"(c[0]), "+f"(c[1]), "+f"(c[2]), "+f"(c[3])
        : "r"(a[0]), "r"(a[1]), "r"(a[2]), "r"(a[3]), "r"(b[0]), "r"(b[1]));
}
__device__ __forceinline__ void ldm4(uint32_t* r, uint32_t addr) {
    asm volatile("ldmatrix.sync.aligned.m8n8.x4.shared.b16 {%0,%1,%2,%3},[%4];"
                 : "=r"(r[0]), "=r"(r[1]), "=r"(r[2]), "=r"(r[3]) : "r"(addr));
}

// ===========================================================================
// bf16x3 MMA GEMM: C[M,N] = A@B, A planes [M][K], B planes [N][K] (pre-T).
// BM=128, BN=128, BK=32, 256 thr (8 warps, 64x32 warp tiles).
// Dynamic smem: A[2buf][2pl][128][40] + B same = 81920 B.
// epi: 0 none, 1 +resid, 3 gelu(.+bias)
// ===========================================================================
#define APLANE (128 * 40)
#define SMEM_MMA (8 * APLANE * 2)   // 8 planes total * 2 bytes

__device__ __forceinline__ void mma_body(
    const bf16* __restrict__ Ah, const bf16* __restrict__ Al,
    const bf16* __restrict__ Bh, const bf16* __restrict__ Bl,
    float* __restrict__ C, int N, int K, int kBeg, int kEnd,
    int epi, const float* __restrict__ bias, const float* __restrict__ resid)
{
    extern __shared__ bf16 sm[];
    const int tid = threadIdx.x;
    const int lane = tid & 31, w = tid >> 5;
    const int wm = w & 1, wn = w >> 1;
    const int row0 = blockIdx.y * 128, col0 = blockIdx.x * 128;

    // global->smem chunk mapping (two 16B chunks per thread per plane)
    const int r1 = tid >> 2,          kc1 = (tid & 3) << 3;
    const int r2 = (tid + 256) >> 2,  kc2 = (tid & 3) << 3;   // rows 64..127

    const bf16* Agh = Ah + (size_t)row0 * K + kBeg;
    const bf16* Agl = Al + (size_t)row0 * K + kBeg;
    const bf16* Bgh = Bh + (size_t)col0 * K + kBeg;
    const bf16* Bgl = Bl + (size_t)col0 * K + kBeg;

    const uint32_t sbase = (uint32_t)__cvta_generic_to_shared(sm);
    // fragment lane offsets
    const int mi = lane >> 3, ri = lane & 7;
    const int a_mo = ((mi & 1) << 3) + ri, a_ko = (mi >> 1) << 3;
    const int b_no = ((mi >> 1) << 3) + ri, b_ko = (mi & 1) << 3;

    float acc[4][4][4];
#pragma unroll
    for (int tm = 0; tm < 4; tm++)
#pragma unroll
        for (int tn = 0; tn < 4; tn++)
#pragma unroll
            for (int e = 0; e < 4; e++) acc[tm][tn][e] = 0.f;

    const int nk = (kEnd - kBeg) >> 5;

    uint4 pa[2][2], pb[2][2];
    // preload tile 0
    pa[0][0] = *(const uint4*)(Agh + (size_t)r1 * K + kc1);
    pa[0][1] = *(const uint4*)(Agh + (size_t)r2 * K + kc2);
    pa[1][0] = *(const uint4*)(Agl + (size_t)r1 * K + kc1);
    pa[1][1] = *(const uint4*)(Agl + (size_t)r2 * K + kc2);
    pb[0][0] = *(const uint4*)(Bgh + (size_t)r1 * K + kc1);
    pb[0][1] = *(const uint4*)(Bgh + (size_t)r2 * K + kc2);
    pb[1][0] = *(const uint4*)(Bgl + (size_t)r1 * K + kc1);
    pb[1][1] = *(const uint4*)(Bgl + (size_t)r2 * K + kc2);
    {
        *(uint4*)(sm + 0 * APLANE + r1 * 40 + kc1) = pa[0][0];
        *(uint4*)(sm + 0 * APLANE + r2 * 40 + kc2) = pa[0][1];
        *(uint4*)(sm + 1 * APLANE + r1 * 40 + kc1) = pa[1][0];
        *(uint4*)(sm + 1 * APLANE + r2 * 40 + kc2) = pa[1][1];
        *(uint4*)(sm + 4 * APLANE + r1 * 40 + kc1) = pb[0][0];
        *(uint4*)(sm + 4 * APLANE + r2 * 40 + kc2) = pb[0][1];
        *(uint4*)(sm + 5 * APLANE + r1 * 40 + kc1) = pb[1][0];
        *(uint4*)(sm + 5 * APLANE + r2 * 40 + kc2) = pb[1][1];
    }
    __syncthreads();

    int buf = 0;
    for (int t = 0; t < nk; t++) {
        const bool more = (t + 1 < nk);
        if (more) {
            const int ko = (t + 1) * 32;
            pa[0][0] = *(const uint4*)(Agh + (size_t)r1 * K + ko + kc1);
            pa[0][1] = *(const uint4*)(Agh + (size_t)r2 * K + ko + kc2);
            pa[1][0] = *(const uint4*)(Agl + (size_t)r1 * K + ko + kc1);
            pa[1][1] = *(const uint4*)(Agl + (size_t)r2 * K + ko + kc2);
            pb[0][0] = *(const uint4*)(Bgh + (size_t)r1 * K + ko + kc1);
            pb[0][1] = *(const uint4*)(Bgh + (size_t)r2 * K + ko + kc2);
            pb[1][0] = *(const uint4*)(Bgl + (size_t)r1 * K + ko + kc1);
            pb[1][1] = *(const uint4*)(Bgl + (size_t)r2 * K + ko + kc2);
        }
        // compute on buf
#pragma unroll
        for (int kk = 0; kk < 32; kk += 16) {
            uint32_t ah[4][4], al[4][4];
#pragma unroll
            for (int tm = 0; tm < 4; tm++) {
                uint32_t ad = sbase + 2u * ((buf * 2) * APLANE
                              + (wm * 64 + tm * 16 + a_mo) * 40 + kk + a_ko);
                ldm4(ah[tm], ad);
                ldm4(al[tm], ad + 2u * APLANE);
            }
            uint32_t bh4[2][4], bl4[2][4];
#pragma unroll
            for (int tp = 0; tp < 2; tp++) {
                uint32_t bd = sbase + 2u * (4 * APLANE + (buf * 2) * APLANE
                              + (wn * 32 + tp * 16 + b_no) * 40 + kk + b_ko);
                ldm4(bh4[tp], bd);
                ldm4(bl4[tp], bd + 2u * APLANE);
            }
#pragma unroll
            for (int tm = 0; tm < 4; tm++)
#pragma unroll
                for (int tn = 0; tn < 4; tn++) {
                    const uint32_t* bh = &bh4[tn >> 1][(tn & 1) * 2];
                    const uint32_t* bl = &bl4[tn >> 1][(tn & 1) * 2];
                    mma16816(acc[tm][tn], ah[tm], bh);
                    mma16816(acc[tm][tn], ah[tm], bl);
                    mma16816(acc[tm][tn], al[tm], bh);
                }
        }
        if (more) {
            const int nb = buf ^ 1;
            *(uint4*)(sm + (nb * 2 + 0) * APLANE + r1 * 40 + kc1) = pa[0][0];
            *(uint4*)(sm + (nb * 2 + 0) * APLANE + r2 * 40 + kc2) = pa[0][1];
            *(uint4*)(sm + (nb * 2 + 1) * APLANE + r1 * 40 + kc1) = pa[1][0];
            *(uint4*)(sm + (nb * 2 + 1) * APLANE + r2 * 40 + kc2) = pa[1][1];
            *(uint4*)(sm + (4 + nb * 2 + 0) * APLANE + r1 * 40 + kc1) = pb[0][0];
            *(uint4*)(sm + (4 + nb * 2 + 0) * APLANE + r2 * 40 + kc2) = pb[0][1];
            *(uint4*)(sm + (4 + nb * 2 + 1) * APLANE + r1 * 40 + kc1) = pb[1][0];
            *(uint4*)(sm + (4 + nb * 2 + 1) * APLANE + r2 * 40 + kc2) = pb[1][1];
        }
        __syncthreads();
        buf ^= 1;
    }

    // epilogue
    const int g = lane >> 2, tig = lane & 3;
#pragma unroll
    for (int tm = 0; tm < 4; tm++)
#pragma unroll
        for (int tn = 0; tn < 4; tn++) {
            const int r = row0 + wm * 64 + tm * 16 + g;
            const int c = col0 + wn * 32 + tn * 8 + tig * 2;
#pragma unroll
            for (int half = 0; half < 2; half++) {
                const int rr = r + half * 8;
                float v0 = acc[tm][tn][half * 2 + 0];
                float v1 = acc[tm][tn][half * 2 + 1];
                if (epi == 3) {
                    v0 += bias[c]; v1 += bias[c + 1];
                    v0 = 0.5f * v0 * (1.0f + erff(v0 * 0.70710678118654752440f));
                    v1 = 0.5f * v1 * (1.0f + erff(v1 * 0.70710678118654752440f));
                }
                if (epi == 1) {
                    v0 += resid[(size_t)rr * N + c];
                    v1 += resid[(size_t)rr * N + c + 1];
                }
                *(float2*)(C + (size_t)rr * N + c) = make_float2(v0, v1);
            }
        }
}

// z-batched (3 problems sharing N, K)
__global__ __launch_bounds__(256) void mmagemm_k(
    const bf16* A0h, const bf16* A0l, const bf16* B0h, const bf16* B0l, float* C0, int M0,
    const bf16* A1h, const bf16* A1l, const bf16* B1h, const bf16* B1l, float* C1, int M1,
    const bf16* A2h, const bf16* A2l, const bf16* B2h, const bf16* B2l, float* C2, int M2,
    int N, int K, int epi, const float* bias, const float* resid)
{
    const int z = blockIdx.z;
    const bf16* Ah = (z == 0) ? A0h : (z == 1) ? A1h : A2h;
    const bf16* Al = (z == 0) ? A0l : (z == 1) ? A1l : A2l;
    const bf16* Bh = (z == 0) ? B0h : (z == 1) ? B1h : B2h;
    const bf16* Bl = (z == 0) ? B0l : (z == 1) ? B1l : B2l;
    float*      C  = (z == 0) ? C0  : (z == 1) ? C1  : C2;
    const int   M  = (z == 0) ? M0  : (z == 1) ? M1  : M2;
    if (blockIdx.y * 128 >= M) return;
    mma_body(Ah, Al, Bh, Bl, C, N, K, 0, K, epi, bias, resid);
}

// split-K variant
__global__ __launch_bounds__(256) void mmagemm_splitk_k(
    const bf16* Ah, const bf16* Al, const bf16* Bh, const bf16* Bl,
    float* Cpart, int M, int N, int K, int KC)
{
    const int z = blockIdx.z;
    mma_body(Ah, Al, Bh, Bl, Cpart + (size_t)z * M * N, N, K, z * KC, z * KC + KC,
             0, nullptr, nullptr);
}

// split-K reduce + epilogue
__global__ void redk_k(const float* __restrict__ parts, int nparts, int total, int N,
                       int epi, const float* __restrict__ bias,
                       const float* __restrict__ resid, float* __restrict__ out)
{
    for (int idx = blockIdx.x * blockDim.x + threadIdx.x; idx < total;
         idx += gridDim.x * blockDim.x) {
        float s = parts[idx];
        for (int p = 1; p < nparts; p++) s += parts[(size_t)p * total + idx];
        const int c = idx % N;
        if (epi == 2) s += bias[c];
        else if (epi == 4) s += bias[c] + resid[idx];
        out[idx] = s;
    }
}

// ---------------------------------------------------------------------------
// bf16 hi/lo conversion kernels
// ---------------------------------------------------------------------------
__global__ void cvt_k(const float* __restrict__ in, bf16* __restrict__ oh,
                      bf16* __restrict__ ol, int n4)
{
    for (int i = blockIdx.x * blockDim.x + threadIdx.x; i < n4;
         i += gridDim.x * blockDim.x) {
        float4 v = ((const float4*)in)[i];
        bf16 h0 = __float2bfloat16(v.x), h1 = __float2bfloat16(v.y);
        bf16 h2 = __float2bfloat16(v.z), h3 = __float2bfloat16(v.w);
        bf16 l0 = __float2bfloat16(v.x - __bfloat162float(h0));
        bf16 l1 = __float2bfloat16(v.y - __bfloat162float(h1));
        bf16 l2 = __float2bfloat16(v.z - __bfloat162float(h2));
        bf16 l3 = __float2bfloat16(v.w - __bfloat162float(h3));
        ((__nv_bfloat162*)oh)[i * 2]     = __halves2bfloat162(h0, h1);
        ((__nv_bfloat162*)oh)[i * 2 + 1] = __halves2bfloat162(h2, h3);
        ((__nv_bfloat162*)ol)[i * 2]     = __halves2bfloat162(l0, l1);
        ((__nv_bfloat162*)ol)[i * 2 + 1] = __halves2bfloat162(l2, l3);
    }
}

// transpose + convert: in [K][N] fp32 (per matrix) -> out [N][K] hi/lo bf16
__global__ void cvtT_k(const float* __restrict__ in, bf16* __restrict__ oh,
                       bf16* __restrict__ ol, int K, int N)
{
    __shared__ float t[32][33];
    const size_t moff = (size_t)blockIdx.z * K * N;
    const int k0 = blockIdx.y * 32, n0 = blockIdx.x * 32;
#pragma unroll
    for (int r = 0; r < 4; r++) {
        const int kr = k0 + threadIdx.y + r * 8;
        t[threadIdx.y + r * 8][threadIdx.x] = in[moff + (size_t)kr * N + n0 + threadIdx.x];
    }
    __syncthreads();
#pragma unroll
    for (int r = 0; r < 4; r++) {
        const int nr = n0 + threadIdx.y + r * 8;
        const int kc = k0 + threadIdx.x;
        const float v = t[threadIdx.x][threadIdx.y + r * 8];
        bf16 h = __float2bfloat16(v);
        bf16 l = __float2bfloat16(v - __bfloat162float(h));
        oh[moff + (size_t)nr * K + kc] = h;
        ol[moff + (size_t)nr * K + kc] = l;
    }
}

// conv_w (layer, o, d, r) -> planes [layer][o][k = r*512 + d]
__global__ void cvt_wc_k(const float* __restrict__ cw, bf16* __restrict__ oh,
                         bf16* __restrict__ ol)
{
    const int total = NLAYERS * DM * (RRATIO * DM);
    for (int idx = blockIdx.x * blockDim.x + threadIdx.x; idx < total;
         idx += gridDim.x * blockDim.x) {
        const int layer = idx / (DM * RRATIO * DM);
        const int rem   = idx % (DM * RRATIO * DM);
        const int o = rem / (RRATIO * DM), kk = rem % (RRATIO * DM);
        const float v = cw[(size_t)layer * DM * RRATIO * DM + (size_t)o * (RRATIO * DM)
                           + (kk & 511) * 4 + (kk >> 9)];
        bf16 h = __float2bfloat16(v);
        oh[idx] = h;
        ol[idx] = __float2bfloat16(v - __bfloat162float(h));
    }
}

// ---------------------------------------------------------------------------
// Attention scores (scalar FFMA2, unchanged)
// ---------------------------------------------------------------------------
__global__ __launch_bounds__(256, 3) void scores_k(
    const float* __restrict__ Q, const float* __restrict__ Kb,
    float* __restrict__ out, int L, int ldb, long bSB, long bSH, float scale,
    int shiftSkip)
{
    const int i0 = blockIdx.y * 64, j0 = blockIdx.x * 64;
    if (shiftSkip && (i0 + j0 <= 384)) return;
    __shared__ __align__(16) float Qs[64][68];
    __shared__ __align__(16) float Ks[64][68];
    const int bh = blockIdx.z, b = bh >> 3, h = bh & 7;
    const float* Qg = Q + ((size_t)(b * SQ + i0)) * DM + h * DH;
    const float* Kg = Kb + (size_t)b * bSB + (size_t)h * bSH + (size_t)j0 * ldb;
    const int tid = threadIdx.x;
    const int rr = tid >> 4, c4 = (tid & 15) << 2;
#pragma unroll
    for (int s = 0; s < 4; s++) {
        const int r = rr + s * 16;
        float4 qv = *(const float4*)(Qg + (size_t)r * DM + c4);
        Qs[c4+0][r] = qv.x; Qs[c4+1][r] = qv.y; Qs[c4+2][r] = qv.z; Qs[c4+3][r] = qv.w;
        float4 kv2 = *(const float4*)(Kg + (size_t)r * ldb + c4);
        Ks[c4+0][r] = kv2.x; Ks[c4+1][r] = kv2.y; Ks[c4+2][r] = kv2.z; Ks[c4+3][r] = kv2.w;
    }
    __syncthreads();
    const int tx = tid & 15, ty = tid >> 4;
    unsigned long long acc[2][4];
#pragma unroll
    for (int m = 0; m < 2; m++)
#pragma unroll
        for (int n = 0; n < 4; n++) acc[m][n] = 0ull;
#pragma unroll
    for (int d = 0; d < 64; d++) {
        const unsigned long long* Ap = (const unsigned long long*)(&Qs[d][ty*4]);
        unsigned long long am0 = Ap[0], am1 = Ap[1];
        float4 bv = *(const float4*)&Ks[d][tx*4];
        unsigned long long bd[4] = { pk2(bv.x, bv.x), pk2(bv.y, bv.y),
                                     pk2(bv.z, bv.z), pk2(bv.w, bv.w) };
#pragma unroll
        for (int n = 0; n < 4; n++) { fma2(acc[0][n], am0, bd[n]); fma2(acc[1][n], am1, bd[n]); }
    }
    float* Og = out + ((long)bh * SQ + i0) * (long)L + j0 + tx * 4;
#pragma unroll
    for (int m2 = 0; m2 < 2; m2++) {
        float lo[4], hi[4];
#pragma unroll
        for (int n = 0; n < 4; n++) upk2(acc[m2][n], lo[n], hi[n]);
        *(float4*)(Og + (long)(ty*4 + 2*m2)     * L) =
            make_float4(lo[0]*scale, lo[1]*scale, lo[2]*scale, lo[3]*scale);
        *(float4*)(Og + (long)(ty*4 + 2*m2 + 1) * L) =
            make_float4(hi[0]*scale, hi[1]*scale, hi[2]*scale, hi[3]*scale);
    }
}

// ---------------------------------------------------------------------------
// AV (scalar FFMA2, unchanged)
// ---------------------------------------------------------------------------
__global__ __launch_bounds__(256, 3) void av_k(
    const float* __restrict__ P, const float* __restrict__ V,
    float* __restrict__ out, int L)
{
    __shared__ __align__(16) float Ps[64][68];
    __shared__ __align__(16) float Vs[64][68];
    const int bh = blockIdx.z, b = bh >> 3, h = bh & 7;
    const int i0 = blockIdx.y * 64;
    const float* Pg = P + ((long)bh * SQ + i0) * (long)L;
    const float* Vg = V + (size_t)b * L * DM + h * DH;
    const int tid = threadIdx.x;
    const int rr = tid >> 4, c4 = (tid & 15) << 2;
    const int tx = tid & 15, ty = tid >> 4;
    unsigned long long acc[2][4];
#pragma unroll
    for (int m = 0; m < 2; m++)
#pragma unroll
        for (int n = 0; n < 4; n++) acc[m][n] = 0ull;
    for (int j0 = 0; j0 < L; j0 += 64) {
#pragma unroll
        for (int s = 0; s < 4; s++) {
            const int r = rr + s * 16;
            float4 pv = *(const float4*)(Pg + (long)r * L + j0 + c4);
            Ps[c4+0][r] = pv.x; Ps[c4+1][r] = pv.y; Ps[c4+2][r] = pv.z; Ps[c4+3][r] = pv.w;
            float4 vv = *(const float4*)(Vg + (size_t)(j0 + r) * DM + c4);
            *(float4*)&Vs[r][c4] = vv;
        }
        __syncthreads();
#pragma unroll
        for (int j = 0; j < 64; j++) {
            const unsigned long long* Ap = (const unsigned long long*)(&Ps[j][ty*4]);
            unsigned long long am0 = Ap[0], am1 = Ap[1];
            float4 bv = *(const float4*)&Vs[j][tx*4];
            unsigned long long bd[4] = { pk2(bv.x, bv.x), pk2(bv.y, bv.y),
                                         pk2(bv.z, bv.z), pk2(bv.w, bv.w) };
#pragma unroll
            for (int n = 0; n < 4; n++) { fma2(acc[0][n], am0, bd[n]); fma2(acc[1][n], am1, bd[n]); }
        }
        __syncthreads();
    }
    float* Og = out + ((size_t)(b * SQ + i0)) * DM + h * DH + tx * 4;
#pragma unroll
    for (int m2 = 0; m2 < 2; m2++) {
        float lo[4], hi[4];
#pragma unroll
        for (int n = 0; n < 4; n++) upk2(acc[m2][n], lo[n], hi[n]);
        *(float4*)(Og + (size_t)(ty*4 + 2*m2)     * DM) = make_float4(lo[0], lo[1], lo[2], lo[3]);
        *(float4*)(Og + (size_t)(ty*4 + 2*m2 + 1) * DM) = make_float4(hi[0], hi[1], hi[2], hi[3]);
    }
}

// ---------------------------------------------------------------------------
// Softmax (optional shifted pos add)
// ---------------------------------------------------------------------------
__global__ __launch_bounds__(128) void softmax_k(
    float* __restrict__ dots, const float* __restrict__ posR, int L, int usePos)
{
    const int i = blockIdx.x, bh = blockIdx.y;
    float* row = dots + ((long)bh * SQ + i) * (long)L;
    const float* prow = posR + ((long)bh * SQ + i) * (long)KVN;
    const int tid = threadIdx.x;
    const int nper = L >> 7;
    float vals[9];
    float mx = -1e30f;
    for (int t = 0; t < nper; t++) {
        const int j = tid + t * 128;
        float vv = row[j];
        if (usePos) {
            const int jp = j + (SQ - 1) - i;
            if (jp < KVN) vv += prow[jp];
        }
        vals[t] = vv;
        mx = fmaxf(mx, vv);
    }
    __shared__ float sh[128];
    sh[tid] = mx; __syncthreads();
    for (int o = 64; o > 0; o >>= 1) { if (tid < o) sh[tid] = fmaxf(sh[tid], sh[tid + o]); __syncthreads(); }
    mx = sh[0]; __syncthreads();
    float s = 0.f;
    for (int t = 0; t < nper; t++) { vals[t] = __expf(vals[t] - mx); s += vals[t]; }
    sh[tid] = s; __syncthreads();
    for (int o = 64; o > 0; o >>= 1) { if (tid < o) sh[tid] += sh[tid + o]; __syncthreads(); }
    const float inv = 1.0f / sh[0];
    for (int t = 0; t < nper; t++) row[tid + t * 128] = vals[t] * inv;
}

// ---------------------------------------------------------------------------
// LayerNorm
// ---------------------------------------------------------------------------
__global__ __launch_bounds__(128) void ln_k(
    const float* __restrict__ x, const float* __restrict__ g,
    const float* __restrict__ bt, float* __restrict__ out)
{
    const int row = blockIdx.x, tid = threadIdx.x;
    const float* xr = x + (size_t)row * DM;
    float v[4]; float s = 0.f, s2 = 0.f;
#pragma unroll
    for (int t = 0; t < 4; t++) { v[t] = xr[tid + t * 128]; s += v[t]; s2 += v[t] * v[t]; }
    __shared__ float sa[128], sb[128];
    sa[tid] = s; sb[tid] = s2; __syncthreads();
    for (int o = 64; o > 0; o >>= 1) { if (tid < o) { sa[tid] += sa[tid+o]; sb[tid] += sb[tid+o]; } __syncthreads(); }
    const float mean = sa[0] * (1.0f / DM);
    const float var  = sb[0] * (1.0f / DM) - mean * mean;
    const float rs   = rsqrtf(var + 1e-5f);
    float* orow = out + (size_t)row * DM;
#pragma unroll
    for (int t = 0; t < 4; t++) {
        const int c = tid + t * 128;
        orow[c] = (v[t] - mean) * rs * g[c] + bt[c];
    }
}

// ---------------------------------------------------------------------------
// Misc kernels
// ---------------------------------------------------------------------------
__global__ void embed_k(const int* __restrict__ trg, const float* __restrict__ emb,
                        float* __restrict__ x)
{
    const int total = MROWS * (DM / 4);
    for (int idx = blockIdx.x * blockDim.x + threadIdx.x; idx < total; idx += gridDim.x * blockDim.x) {
        const int row = idx >> 7, c = idx & 127;
        ((float4*)x)[idx] = ((const float4*)emb)[(size_t)trg[row] * 128 + c];
    }
}

__global__ void kvbuild_k(const float* __restrict__ cm, const float* __restrict__ mem,
                          const float* __restrict__ x, float* __restrict__ kv)
{
    const int row = blockIdx.x;
    const int b = row / KVN, p = row % KVN;
    const float* src;
    if (p < CMEMN)             src = cm  + ((size_t)b * CMEMN + p) * DM;
    else if (p < CMEMN + MEMN) src = mem + ((size_t)b * MEMN + (p - CMEMN)) * DM;
    else                       src = x   + ((size_t)b * SQ + (p - CMEMN - MEMN)) * DM;
    ((float4*)(kv + (size_t)row * DM))[threadIdx.x] = ((const float4*)src)[threadIdx.x];
}

__global__ __launch_bounds__(256) void mse_k(const float* __restrict__ a,
                                             const float* __restrict__ b,
                                             float* __restrict__ part)
{
    __shared__ float sh[256];
    float s = 0.f;
    for (int idx = blockIdx.x * 256 + threadIdx.x; idx < MROWS * DM; idx += 128 * 256) {
        const float d = a[idx] - b[idx];
        s += d * d;
    }
    sh[threadIdx.x] = s; __syncthreads();
    for (int o = 128; o > 0; o >>= 1) { if (threadIdx.x < o) sh[threadIdx.x] += sh[threadIdx.x + o]; __syncthreads(); }
    if (threadIdx.x == 0) part[blockIdx.x] = sh[0];
}

__global__ void copyout_k(const float* __restrict__ x, float* __restrict__ out)
{
    const int total = MROWS * (DM / 4);
    for (int idx = blockIdx.x * blockDim.x + threadIdx.x; idx < total; idx += gridDim.x * blockDim.x)
        ((float4*)out)[idx] = ((const float4*)x)[idx];
}

__global__ __launch_bounds__(128) void loss_k(const float* __restrict__ part,
                                              float* __restrict__ out, int out_size)
{
    __shared__ float sh[128];
    float s = 0.f;
    for (int j = threadIdx.x; j < NLAYERS * 128; j += 128) s += part[j];
    sh[threadIdx.x] = s; __syncthreads();
    for (int o = 64; o > 0; o >>= 1) { if (threadIdx.x < o) sh[threadIdx.x] += sh[threadIdx.x + o]; __syncthreads(); }
    if (threadIdx.x == 0 && out_size > MROWS * DM)
        out[MROWS * DM] = sh[0] * (1.0f / ((float)(MROWS * DM) * (float)NLAYERS));
}

// ---------------------------------------------------------------------------
// Host driver
// ---------------------------------------------------------------------------
extern "C" void kernel_launch(void* const* d_in, const int* in_sizes, int n_in,
                              void* d_out, int out_size)
{
    (void)in_sizes; (void)n_in;
    const int*   trg     = (const int*)  d_in[0];
    const float* latent  = (const float*)d_in[3];
    const float* mems    = (const float*)d_in[4];
    const float* cmems   = (const float*)d_in[5];
    const float* pos_emb = (const float*)d_in[6];
    const float* embed   = (const float*)d_in[7];
    const float* W_self  = (const float*)d_in[8];
    const float* ln1_g   = (const float*)d_in[9];
    const float* ln1_b   = (const float*)d_in[10];
    const float* conv_w  = (const float*)d_in[11];
    const float* conv_b  = (const float*)d_in[12];
    const float* W_src   = (const float*)d_in[13];
    const float* ln2_g   = (const float*)d_in[14];
    const float* ln2_b   = (const float*)d_in[15];
    const float* w1      = (const float*)d_in[16];
    const float* b1      = (const float*)d_in[17];
    const float* w2      = (const float*)d_in[18];
    const float* b2      = (const float*)d_in[19];

    float *x,*kv,*q,*k,*v,*dots,*pos,*ao,*t1,*t2,*cm,*kcm,*vcm,*y,*ff,*sk,*part;
    cudaGetSymbolAddress((void**)&x,   g_x);
    cudaGetSymbolAddress((void**)&kv,  g_kv);
    cudaGetSymbolAddress((void**)&q,   g_q);
    cudaGetSymbolAddress((void**)&k,   g_k);
    cudaGetSymbolAddress((void**)&v,   g_v);
    cudaGetSymbolAddress((void**)&dots,g_dots);
    cudaGetSymbolAddress((void**)&pos, g_pos);
    cudaGetSymbolAddress((void**)&ao,  g_ao);
    cudaGetSymbolAddress((void**)&t1,  g_t1);
    cudaGetSymbolAddress((void**)&t2,  g_t2);
    cudaGetSymbolAddress((void**)&cm,  g_cm);
    cudaGetSymbolAddress((void**)&kcm, g_kcm);
    cudaGetSymbolAddress((void**)&vcm, g_vcm);
    cudaGetSymbolAddress((void**)&y,   g_y);
    cudaGetSymbolAddress((void**)&ff,  g_ff);
    cudaGetSymbolAddress((void**)&sk,  g_sk);
    cudaGetSymbolAddress((void**)&part,g_part);

    bf16 *xh,*xl,*kvh,*kvl,*aoh,*aol,*yh,*yl,*ffh,*ffl,*cmh,*cml,*msh,*msl,*lth,*ltl;
    bf16 *Wsh,*Wsl,*Wrh,*Wrl,*w1h,*w1l,*w2h,*w2l,*wch,*wcl;
    cudaGetSymbolAddress((void**)&xh,  g_xh);  cudaGetSymbolAddress((void**)&xl,  g_xl);
    cudaGetSymbolAddress((void**)&kvh, g_kvh); cudaGetSymbolAddress((void**)&kvl, g_kvl);
    cudaGetSymbolAddress((void**)&aoh, g_aoh); cudaGetSymbolAddress((void**)&aol, g_aol);
    cudaGetSymbolAddress((void**)&yh,  g_yh);  cudaGetSymbolAddress((void**)&yl,  g_yl);
    cudaGetSymbolAddress((void**)&ffh, g_ffh); cudaGetSymbolAddress((void**)&ffl, g_ffl);
    cudaGetSymbolAddress((void**)&cmh, g_cmh); cudaGetSymbolAddress((void**)&cml, g_cml);
    cudaGetSymbolAddress((void**)&msh, g_msh); cudaGetSymbolAddress((void**)&msl, g_msl);
    cudaGetSymbolAddress((void**)&lth, g_lth); cudaGetSymbolAddress((void**)&ltl, g_ltl);
    cudaGetSymbolAddress((void**)&Wsh, g_Wsh); cudaGetSymbolAddress((void**)&Wsl, g_Wsl);
    cudaGetSymbolAddress((void**)&Wrh, g_Wrh); cudaGetSymbolAddress((void**)&Wrl, g_Wrl);
    cudaGetSymbolAddress((void**)&w1h, g_w1h); cudaGetSymbolAddress((void**)&w1l, g_w1l);
    cudaGetSymbolAddress((void**)&w2h, g_w2h); cudaGetSymbolAddress((void**)&w2l, g_w2l);
    cudaGetSymbolAddress((void**)&wch, g_wch); cudaGetSymbolAddress((void**)&wcl, g_wcl);

    cudaFuncSetAttribute(mmagemm_k, cudaFuncAttributeMaxDynamicSharedMemorySize, SMEM_MMA);
    cudaFuncSetAttribute(mmagemm_splitk_k, cudaFuncAttributeMaxDynamicSharedMemorySize, SMEM_MMA);

    // ---- one-time (per call) conversions ----
    embed_k<<<256, 256>>>(trg, embed, x);
    cvtT_k<<<dim3(16, 16, 16), dim3(32, 8)>>>(W_self, Wsh, Wsl, DM, DM);
    cvtT_k<<<dim3(16, 16, 16), dim3(32, 8)>>>(W_src,  Wrh, Wrl, DM, DM);
    cvtT_k<<<dim3(64, 16, 4),  dim3(32, 8)>>>(w1, w1h, w1l, DM, FFD);
    cvtT_k<<<dim3(16, 64, 4),  dim3(32, 8)>>>(w2, w2h, w2l, FFD, DM);
    cvt_wc_k<<<2048, 256>>>(conv_w, wch, wcl);
    cvt_k<<<2048, 256>>>(mems,   msh, msl, NLAYERS * NB * MEMN * DM / 4);
    cvt_k<<<512,  256>>>(latent, lth, ltl, NB * LLAT * DM / 4);

    const size_t WS = (size_t)DM * DM;
    for (int i = 0; i < NLAYERS; i++) {
        const bf16* Wqh = Wsh + (i*4+0)*WS; const bf16* Wql = Wsl + (i*4+0)*WS;
        const bf16* Wkh = Wsh + (i*4+1)*WS; const bf16* Wkl = Wsl + (i*4+1)*WS;
        const bf16* Wvh = Wsh + (i*4+2)*WS; const bf16* Wvl = Wsl + (i*4+2)*WS;
        const bf16* Woh = Wsh + (i*4+3)*WS; const bf16* Wol = Wsl + (i*4+3)*WS;
        const bf16* Xqh = Wrh + (i*4+0)*WS; const bf16* Xql = Wrl + (i*4+0)*WS;
        const bf16* Xkh = Wrh + (i*4+1)*WS; const bf16* Xkl = Wrl + (i*4+1)*WS;
        const bf16* Xvh = Wrh + (i*4+2)*WS; const bf16* Xvl = Wrl + (i*4+2)*WS;
        const bf16* Xoh = Wrh + (i*4+3)*WS; const bf16* Xol = Wrl + (i*4+3)*WS;
        const bf16* msh_i = msh + (size_t)i * NB * MEMN * DM;
        const bf16* msl_i = msl + (size_t)i * NB * MEMN * DM;
        const float* mems_i  = mems  + (size_t)i * NB * MEMN * DM;
        const float* cmems_i = cmems + (size_t)i * NB * CMEMN * DM;

        // ---- self attention ----
        kvbuild_k<<<NB * KVN, 128>>>(cmems_i, mems_i, x, kv);
        cvt_k<<<1024, 256>>>(x,  xh,  xl,  MROWS * DM / 4);
        cvt_k<<<2048, 256>>>(kv, kvh, kvl, NB * KVN * DM / 4);
        mmagemm_k<<<dim3(4, 36, 3), 256, SMEM_MMA>>>(
            xh,  xl,  Wqh, Wql, q, MROWS,
            kvh, kvl, Wkh, Wkl, k, NB * KVN,
            kvh, kvl, Wvh, Wvl, v, NB * KVN,
            DM, DM, 0, nullptr, nullptr);
        scores_k<<<dim3(18, 8, 32), 256>>>(q, k,       dots, KVN, DM, (long)KVN * DM, 64,             0.125f, 0);
        scores_k<<<dim3(18, 8, 32), 256>>>(q, pos_emb, pos,  KVN, DH, 0,              (long)KVN * DH, 8.0f,   1);
        softmax_k<<<dim3(SQ, 32), 128>>>(dots, pos, KVN, 1);
        av_k<<<dim3(1, 8, 32), 256>>>(dots, v, ao, KVN);
        cvt_k<<<1024, 256>>>(ao, aoh, aol, MROWS * DM / 4);
        mmagemm_k<<<dim3(4, 16, 1), 256, SMEM_MMA>>>(
            aoh, aol, Woh, Wol, y, MROWS,
            aoh, aol, Woh, Wol, y, 0,
            aoh, aol, Woh, Wol, y, 0,
            DM, DM, 1, nullptr, x);                 // + residual x
        ln_k<<<MROWS, 128>>>(y, ln1_g + i * DM, ln1_b + i * DM, x);
        cvt_k<<<1024, 256>>>(x, xh, xl, MROWS * DM / 4);   // post-ln x

        // ---- conv compress (split-K=4) ----
        mmagemm_splitk_k<<<dim3(4, 4, 4), 256, SMEM_MMA>>>(
            msh_i, msl_i, wch + (size_t)i * DM * FFD, wcl + (size_t)i * DM * FFD,
            sk, NB * CMEMN, DM, RRATIO * DM, DM);
        redk_k<<<256, 256>>>(sk, 4, NB * CMEMN * DM, DM, 2, conv_b + i * DM, nullptr, cm);
        cvt_k<<<256, 256>>>(cm, cmh, cml, NB * CMEMN * DM / 4);

        // ---- reconstruction attention loss ----
        mmagemm_k<<<dim3(4, 16, 3), 256, SMEM_MMA>>>(
            xh,    xl,    Wqh, Wql, q, MROWS,
            msh_i, msl_i, Wkh, Wkl, k, MROWS,
            msh_i, msl_i, Wvh, Wvl, v, MROWS,
            DM, DM, 0, nullptr, nullptr);
        scores_k<<<dim3(8, 8, 32), 256>>>(q, k, dots, MEMN, DM, (long)MEMN * DM, 64, 0.125f, 0);
        softmax_k<<<dim3(SQ, 32), 128>>>(dots, pos, MEMN, 0);
        av_k<<<dim3(1, 8, 32), 256>>>(dots, v, t1, MEMN);
        mmagemm_k<<<dim3(4, 4, 2), 256, SMEM_MMA>>>(
            cmh, cml, Wkh, Wkl, kcm, NB * CMEMN,
            cmh, cml, Wvh, Wvl, vcm, NB * CMEMN,
            cmh, cml, Wvh, Wvl, vcm, 0,
            DM, DM, 0, nullptr, nullptr);
        scores_k<<<dim3(2, 8, 32), 256>>>(q, kcm, dots, CMEMN, DM, (long)CMEMN * DM, 64, 0.125f, 0);
        softmax_k<<<dim3(SQ, 32), 128>>>(dots, pos, CMEMN, 0);
        av_k<<<dim3(1, 8, 32), 256>>>(dots, vcm, t2, CMEMN);
        mse_k<<<128, 256>>>(t1, t2, part + i * 128);

        // ---- cross attention to latent ----
        mmagemm_k<<<dim3(4, 16, 3), 256, SMEM_MMA>>>(
            xh,  xl,  Xqh, Xql, q, MROWS,
            lth, ltl, Xkh, Xkl, k, NB * LLAT,
            lth, ltl, Xvh, Xvl, v, NB * LLAT,
            DM, DM, 0, nullptr, nullptr);
        scores_k<<<dim3(4, 8, 32), 256>>>(q, k, dots, LLAT, DM, (long)LLAT * DM, 64, 0.125f, 0);
        softmax_k<<<dim3(SQ, 32), 128>>>(dots, pos, LLAT, 0);
        av_k<<<dim3(1, 8, 32), 256>>>(dots, v, ao, LLAT);
        cvt_k<<<1024, 256>>>(ao, aoh, aol, MROWS * DM / 4);
        mmagemm_k<<<dim3(4, 16, 1), 256, SMEM_MMA>>>(
            aoh, aol, Xoh, Xol, x, MROWS,
            aoh, aol, Xoh, Xol, x, 0,
            aoh, aol, Xoh, Xol, x, 0,
            DM, DM, 0, nullptr, nullptr);

        // ---- feed-forward ----
        ln_k<<<MROWS, 128>>>(x, ln2_g + i * DM, ln2_b + i * DM, y);
        cvt_k<<<1024, 256>>>(y, yh, yl, MROWS * DM / 4);
        mmagemm_k<<<dim3(16, 16, 1), 256, SMEM_MMA>>>(
            yh, yl, w1h + (size_t)i * DM * FFD, w1l + (size_t)i * DM * FFD, ff, MROWS,
            yh, yl, nullptr, nullptr, ff, 0,
            yh, yl, nullptr, nullptr, ff, 0,
            FFD, DM, 3, b1 + (size_t)i * FFD, nullptr);
        cvt_k<<<2048, 256>>>(ff, ffh, ffl, MROWS * FFD / 4);
        mmagemm_splitk_k<<<dim3(4, 16, 2), 256, SMEM_MMA>>>(
            ffh, ffl, w2h + (size_t)i * FFD * DM, w2l + (size_t)i * FFD * DM,
            sk, MROWS, DM, FFD, FFD / 2);
        redk_k<<<512, 256>>>(sk, 2, MROWS * DM, DM, 4, b2 + i * DM, x, x);
    }

    copyout_k<<<512, 256>>>(x, (float*)d_out);
    loss_k<<<1, 128>>>(part, (float*)d_out, out_size);
}